// round 8
// baseline (speedup 1.0000x reference)
#include <cuda_runtime.h>
#include <cuda_bf16.h>
#include <cuda_fp16.h>
#include <math.h>
#include <stddef.h>
#include <stdint.h>

// Problem constants
#define Bb 4
#define Nn 2048
#define Dd 256
#define Hh 8
#define dhd 32
#define M_ROWS (Bb * Nn)            // 8192
#define EPSc 1e-5f
#define SCALEc 0.17677669529663687f // 1/sqrt(32)
#define SC2 (0.17677669529663687f * 1.4426950408889634f) // scale * log2(e)

// ---------------- scratch (device globals; no allocation allowed) ----------
__device__ float g_h[M_ROWS * Dd];
__device__ float g_qkv[M_ROWS * 3 * Dd];
__device__ __nv_bfloat16 g_qb[Bb * Hh * Nn * dhd];  // q * SC2, bf16
__device__ __nv_bfloat16 g_kb[Bb * Hh * Nn * dhd];
__device__ __half g_vh[Bb * Hh * Nn * dhd];         // v, f16
__device__ float g_attn[M_ROWS * Dd];
__device__ float g_x2[M_ROWS * Dd];
__device__ float g_t[M_ROWS * 2 * Dd];

// ---------------- mma helpers ----------------------------------------------
__device__ __forceinline__ void mma16816(float* c, const uint32_t* a,
                                         const uint32_t* b) {
    asm volatile(
        "mma.sync.aligned.m16n8k16.row.col.f32.bf16.bf16.f32 "
        "{%0,%1,%2,%3}, {%4,%5,%6,%7}, {%8,%9}, {%0,%1,%2,%3};"
        : "+f"(c[0]), "+f"(c[1]), "+f"(c[2]), "+f"(c[3])
        : "r"(a[0]), "r"(a[1]), "r"(a[2]), "r"(a[3]), "r"(b[0]), "r"(b[1]));
}
__device__ __forceinline__ void mma16816h(float* c, const uint32_t* a,
                                          const uint32_t* b) {
    asm volatile(
        "mma.sync.aligned.m16n8k16.row.col.f32.f16.f16.f32 "
        "{%0,%1,%2,%3}, {%4,%5,%6,%7}, {%8,%9}, {%0,%1,%2,%3};"
        : "+f"(c[0]), "+f"(c[1]), "+f"(c[2]), "+f"(c[3])
        : "r"(a[0]), "r"(a[1]), "r"(a[2]), "r"(a[3]), "r"(b[0]), "r"(b[1]));
}
__device__ __forceinline__ void mma_tf32(float* c, const uint32_t* a,
                                         const uint32_t* b) {
    asm volatile(
        "mma.sync.aligned.m16n8k8.row.col.f32.tf32.tf32.f32 "
        "{%0,%1,%2,%3}, {%4,%5,%6,%7}, {%8,%9}, {%0,%1,%2,%3};"
        : "+f"(c[0]), "+f"(c[1]), "+f"(c[2]), "+f"(c[3])
        : "r"(a[0]), "r"(a[1]), "r"(a[2]), "r"(a[3]), "r"(b[0]), "r"(b[1]));
}
__device__ __forceinline__ uint32_t f2tf32(float f) {
    uint32_t r;
    asm("cvt.rna.tf32.f32 %0, %1;" : "=r"(r) : "f"(f));
    return r;
}

// ---------------- LayerNorm -------------------------------------------------
__global__ void __launch_bounds__(256) ln_kernel(const float* __restrict__ x,
                                                 const float* __restrict__ g,
                                                 const float* __restrict__ b,
                                                 float* __restrict__ out) {
    int row = blockIdx.x * 8 + (threadIdx.x >> 5);
    int lane = threadIdx.x & 31;
    const float4* xr = (const float4*)(x + (size_t)row * Dd);
    float4 v0 = xr[lane];
    float4 v1 = xr[lane + 32];
    float s = v0.x + v0.y + v0.z + v0.w + v1.x + v1.y + v1.z + v1.w;
#pragma unroll
    for (int o = 16; o; o >>= 1) s += __shfl_xor_sync(0xffffffffu, s, o);
    float mu = s * (1.0f / Dd);
    float a0 = v0.x - mu, a1 = v0.y - mu, a2 = v0.z - mu, a3 = v0.w - mu;
    float a4 = v1.x - mu, a5 = v1.y - mu, a6 = v1.z - mu, a7 = v1.w - mu;
    float ss = a0 * a0 + a1 * a1 + a2 * a2 + a3 * a3 + a4 * a4 + a5 * a5 +
               a6 * a6 + a7 * a7;
#pragma unroll
    for (int o = 16; o; o >>= 1) ss += __shfl_xor_sync(0xffffffffu, ss, o);
    float inv = rsqrtf(ss * (1.0f / Dd) + EPSc);
    const float4* g4 = (const float4*)g;
    const float4* b4 = (const float4*)b;
    float4 g0 = g4[lane], g1 = g4[lane + 32];
    float4 bb0 = b4[lane], bb1 = b4[lane + 32];
    float4* o4 = (float4*)(out + (size_t)row * Dd);
    o4[lane] = make_float4(a0 * inv * g0.x + bb0.x, a1 * inv * g0.y + bb0.y,
                           a2 * inv * g0.z + bb0.z, a3 * inv * g0.w + bb0.w);
    o4[lane + 32] = make_float4(a4 * inv * g1.x + bb1.x, a5 * inv * g1.y + bb1.y,
                                a6 * inv * g1.z + bb1.z, a7 * inv * g1.w + bb1.w);
}

// ---------------- tf32 tensor-core GEMM with register prefetch --------------
// Block tile 128Mx64N, BK=32, 256 thr (8 warps 4x2), warp tile 32x32.
template <bool RELU, bool RES>
__global__ void __launch_bounds__(256) gemm_tc(const float* __restrict__ A,
                                               const float* __restrict__ W,
                                               const float* __restrict__ bias,
                                               const float* __restrict__ res,
                                               float* __restrict__ C,
                                               int M, int K, int Nc) {
    __shared__ uint32_t As[128][36];
    __shared__ uint32_t Ws[32][68];
    int tid = threadIdx.x;
    int w = tid >> 5, lane = tid & 31;
    int g = lane >> 2, t = lane & 3;
    int wm = (w & 3) * 32, wn = (w >> 2) * 32;
    int row0 = blockIdx.y * 128, col0 = blockIdx.x * 64;

    float c[2][4][4] = {};

    int arow = tid >> 1, acol = (tid & 1) * 16;
    int wrow = tid >> 3, wcol = (tid & 7) * 8;
    const float* apg = A + (size_t)(row0 + arow) * K + acol;
    const float* wpg = W + (size_t)wrow * Nc + col0 + wcol;

    // prefetch first tile into registers
    float4 aR[4], wR[2];
#pragma unroll
    for (int j = 0; j < 4; j++) aR[j] = *(const float4*)(apg + j * 4);
#pragma unroll
    for (int j = 0; j < 2; j++) wR[j] = *(const float4*)(wpg + j * 4);

    for (int k0 = 0; k0 < K; k0 += 32) {
        // stage current tile (cvt to tf32)
#pragma unroll
        for (int j = 0; j < 4; j++) {
            As[arow][acol + j * 4 + 0] = f2tf32(aR[j].x);
            As[arow][acol + j * 4 + 1] = f2tf32(aR[j].y);
            As[arow][acol + j * 4 + 2] = f2tf32(aR[j].z);
            As[arow][acol + j * 4 + 3] = f2tf32(aR[j].w);
        }
#pragma unroll
        for (int j = 0; j < 2; j++) {
            Ws[wrow][wcol + j * 4 + 0] = f2tf32(wR[j].x);
            Ws[wrow][wcol + j * 4 + 1] = f2tf32(wR[j].y);
            Ws[wrow][wcol + j * 4 + 2] = f2tf32(wR[j].z);
            Ws[wrow][wcol + j * 4 + 3] = f2tf32(wR[j].w);
        }
        __syncthreads();
        // prefetch next tile (hidden behind compute)
        if (k0 + 32 < K) {
#pragma unroll
            for (int j = 0; j < 4; j++)
                aR[j] = *(const float4*)(apg + k0 + 32 + j * 4);
#pragma unroll
            for (int j = 0; j < 2; j++)
                wR[j] = *(const float4*)(wpg + (size_t)(k0 + 32) * Nc + j * 4);
        }
#pragma unroll
        for (int kb = 0; kb < 32; kb += 8) {
            uint32_t a[2][4], b[4][2];
#pragma unroll
            for (int i = 0; i < 2; i++) {
                a[i][0] = As[wm + i * 16 + g][kb + t];
                a[i][1] = As[wm + i * 16 + g + 8][kb + t];
                a[i][2] = As[wm + i * 16 + g][kb + t + 4];
                a[i][3] = As[wm + i * 16 + g + 8][kb + t + 4];
            }
#pragma unroll
            for (int j = 0; j < 4; j++) {
                b[j][0] = Ws[kb + t][wn + j * 8 + g];
                b[j][1] = Ws[kb + t + 4][wn + j * 8 + g];
            }
#pragma unroll
            for (int i = 0; i < 2; i++)
#pragma unroll
                for (int j = 0; j < 4; j++) mma_tf32(c[i][j], a[i], b[j]);
        }
        __syncthreads();
    }

#pragma unroll
    for (int i = 0; i < 2; i++) {
        int r = row0 + wm + i * 16 + g;
#pragma unroll
        for (int j = 0; j < 4; j++) {
            int cc = col0 + wn + j * 8 + 2 * t;
            float2 bv = *(const float2*)(bias + cc);
            float v0 = c[i][j][0] + bv.x, v1 = c[i][j][1] + bv.y;
            float v2 = c[i][j][2] + bv.x, v3 = c[i][j][3] + bv.y;
            if (RELU) {
                v0 = fmaxf(v0, 0.f); v1 = fmaxf(v1, 0.f);
                v2 = fmaxf(v2, 0.f); v3 = fmaxf(v3, 0.f);
            }
            if (RES) {
                float2 r0 = *(const float2*)(res + (size_t)r * Nc + cc);
                float2 r1 = *(const float2*)(res + (size_t)(r + 8) * Nc + cc);
                v0 += r0.x; v1 += r0.y; v2 += r1.x; v3 += r1.y;
            }
            *(float2*)(C + (size_t)r * Nc + cc) = make_float2(v0, v1);
            *(float2*)(C + (size_t)(r + 8) * Nc + cc) = make_float2(v2, v3);
        }
    }
}

// ---------------- RoPE + transpose: q*SC2 bf16, k bf16, v f16 ---------------
__global__ void __launch_bounds__(256) rope_kernel(const float* __restrict__ qkv,
                                                   const float* __restrict__ fc,
                                                   const float* __restrict__ fs,
                                                   __nv_bfloat16* __restrict__ q,
                                                   __nv_bfloat16* __restrict__ k,
                                                   __half* __restrict__ v) {
    int row = blockIdx.x * 8 + (threadIdx.x >> 5);  // (b*H + h)*N + n
    int lane = threadIdx.x & 31;
    int n = row & (Nn - 1);
    int h = (row >> 11) & (Hh - 1);
    int b = row >> 14;
    const float* src = qkv + ((size_t)(b * Nn + n)) * (3 * Dd) + h * dhd;
    size_t obase = (size_t)row * dhd;
    if (lane < 16) {
        float c = fc[n * 16 + lane];
        float sn = fs[n * 16 + lane];
        float qe = src[2 * lane], qo = src[2 * lane + 1];
        q[obase + 2 * lane] = __float2bfloat16((qe * c - qo * sn) * SC2);
        q[obase + 2 * lane + 1] = __float2bfloat16((qe * sn + qo * c) * SC2);
        float ke = src[256 + 2 * lane], ko = src[256 + 2 * lane + 1];
        k[obase + 2 * lane] = __float2bfloat16(ke * c - ko * sn);
        k[obase + 2 * lane + 1] = __float2bfloat16(ke * sn + ko * c);
    }
    v[obase + lane] = __float2half(src[512 + lane]);
}

// ---------------- FA2 flash attention: bf16 S, f16 exp + PV -----------------
// Block: 128 thr (4 warps), 64 q-rows. Row-sum l via ones-column MMA.
__global__ void __launch_bounds__(128) attn_mma_kernel(
    const __nv_bfloat16* __restrict__ Q,
    const __nv_bfloat16* __restrict__ K,
    const __half* __restrict__ V,
    float* __restrict__ Out) {
    __shared__ __nv_bfloat16 Ks[64][40];
    __shared__ __half Vt[32][72];

    int tid = threadIdx.x;
    int w = tid >> 5;
    int lane = tid & 31;
    int g = lane >> 2;
    int t = lane & 3;
    int bh = blockIdx.y;
    int q0 = blockIdx.x * 64;

    const __nv_bfloat16* Kb = K + (size_t)bh * Nn * dhd;
    const __half* Vb = V + (size_t)bh * Nn * dhd;

    int qrow = q0 + w * 16 + g;
    const __nv_bfloat16* Qr0 = Q + ((size_t)bh * Nn + qrow) * dhd;
    const __nv_bfloat16* Qr8 = Qr0 + 8 * dhd;
    uint32_t aQ[8];
#pragma unroll
    for (int ks = 0; ks < 2; ks++) {
        aQ[ks * 4 + 0] = *(const uint32_t*)(Qr0 + ks * 16 + 2 * t);
        aQ[ks * 4 + 1] = *(const uint32_t*)(Qr8 + ks * 16 + 2 * t);
        aQ[ks * 4 + 2] = *(const uint32_t*)(Qr0 + ks * 16 + 2 * t + 8);
        aQ[ks * 4 + 3] = *(const uint32_t*)(Qr8 + ks * 16 + 2 * t + 8);
    }

    float oacc[4][4] = {};
    float oL[4] = {};  // ones-column accumulator: oL[0]=l(row g), oL[2]=l(row g+8) at t==0
    const uint32_t bONE = (g == 0) ? 0x3C003C00u : 0u;  // f16 ones col (n==0)
    uint32_t bL[2] = {bONE, bONE};

    for (int t0 = 0; t0 < Nn; t0 += 64) {
        // K tile: 64x32 bf16 = 256 x 16B, 128 thr -> 2 each
#pragma unroll
        for (int i = 0; i < 2; i++) {
            int chunk = tid + i * 128;
            int row = chunk >> 2, c = chunk & 3;
            uint4 v4 = *(const uint4*)(Kb + (size_t)(t0 + row) * dhd + c * 8);
            *(uint4*)(&Ks[row][c * 8]) = v4;
        }
        // V tile transposed: Vt[d][key], f16
#pragma unroll
        for (int i = 0; i < 16; i++) {
            int e = tid + 128 * i;
            int key = e >> 5, dc = e & 31;
            Vt[dc][key] = Vb[(size_t)(t0 + key) * dhd + dc];
        }
        __syncthreads();

        // S = Qsc K^T (bf16)
        float cS[8][4];
#pragma unroll
        for (int n = 0; n < 8; n++) {
            cS[n][0] = cS[n][1] = cS[n][2] = cS[n][3] = 0.f;
            const __nv_bfloat16* kr = &Ks[n * 8 + g][0];
#pragma unroll
            for (int ks = 0; ks < 2; ks++) {
                uint32_t b[2];
                b[0] = *(const uint32_t*)(kr + ks * 16 + 2 * t);
                b[1] = *(const uint32_t*)(kr + ks * 16 + 2 * t + 8);
                mma16816(cS[n], &aQ[ks * 4], b);
            }
        }

        // p = exp2(S) in f16x2 (S pre-scaled by SC2 via Q)
        uint32_t pf[8][2];
#pragma unroll
        for (int n = 0; n < 8; n++) {
            __half2 lo = h2exp2(__floats2half2_rn(cS[n][0], cS[n][1]));
            __half2 hi = h2exp2(__floats2half2_rn(cS[n][2], cS[n][3]));
            pf[n][0] = *(uint32_t*)&lo;
            pf[n][1] = *(uint32_t*)&hi;
        }

        // O += P V (f16), plus ones-column for row sums
#pragma unroll
        for (int kk = 0; kk < 4; kk++) {
            uint32_t aP[4] = {pf[2 * kk][0], pf[2 * kk][1],
                              pf[2 * kk + 1][0], pf[2 * kk + 1][1]};
#pragma unroll
            for (int nd = 0; nd < 4; nd++) {
                const __half* vr = &Vt[nd * 8 + g][0];
                uint32_t b[2];
                b[0] = *(const uint32_t*)(vr + kk * 16 + 2 * t);
                b[1] = *(const uint32_t*)(vr + kk * 16 + 2 * t + 8);
                mma16816h(oacc[nd], aP, b);
            }
            mma16816h(oL, aP, bL);
        }
        __syncthreads();
    }

    // broadcast row sums from t==0 lane of each group
    float l0 = __shfl_sync(0xffffffffu, oL[0], lane & 28);
    float l1 = __shfl_sync(0xffffffffu, oL[2], lane & 28);
    float inv0 = 1.0f / l0;
    float inv1 = 1.0f / l1;

    int b = bh >> 3, h = bh & 7;
    size_t base0 = ((size_t)(b * Nn + qrow)) * Dd + h * dhd;
    size_t base1 = base0 + 8 * Dd;
#pragma unroll
    for (int nd = 0; nd < 4; nd++) {
        int col = nd * 8 + 2 * t;
        *(float2*)(Out + base0 + col) =
            make_float2(oacc[nd][0] * inv0, oacc[nd][1] * inv0);
        *(float2*)(Out + base1 + col) =
            make_float2(oacc[nd][2] * inv1, oacc[nd][3] * inv1);
    }
}

// ---------------- launch ---------------------------------------------------
extern "C" void kernel_launch(void* const* d_in, const int* in_sizes, int n_in,
                              void* d_out, int out_size) {
    const float* x      = (const float*)d_in[0];
    const float* fc     = (const float*)d_in[1];
    const float* fs     = (const float*)d_in[2];
    const float* w_qkv  = (const float*)d_in[3];
    const float* b_qkv  = (const float*)d_in[4];
    const float* w_proj = (const float*)d_in[5];
    const float* b_proj = (const float*)d_in[6];
    const float* ln1g   = (const float*)d_in[7];
    const float* ln1b   = (const float*)d_in[8];
    const float* ln2g   = (const float*)d_in[9];
    const float* ln2b   = (const float*)d_in[10];
    const float* w1     = (const float*)d_in[11];
    const float* b1     = (const float*)d_in[12];
    const float* w2     = (const float*)d_in[13];
    const float* b2     = (const float*)d_in[14];
    float* out = (float*)d_out;

    float *h, *qkv, *attn, *x2, *t;
    __nv_bfloat16 *qb, *kb;
    __half *vh;
    cudaGetSymbolAddress((void**)&h, g_h);
    cudaGetSymbolAddress((void**)&qkv, g_qkv);
    cudaGetSymbolAddress((void**)&qb, g_qb);
    cudaGetSymbolAddress((void**)&kb, g_kb);
    cudaGetSymbolAddress((void**)&vh, g_vh);
    cudaGetSymbolAddress((void**)&attn, g_attn);
    cudaGetSymbolAddress((void**)&x2, g_x2);
    cudaGetSymbolAddress((void**)&t, g_t);

    // 1) LN1
    ln_kernel<<<M_ROWS / 8, 256>>>(x, ln1g, ln1b, h);
    // 2) QKV gemm (tf32 TC)
    gemm_tc<false, false><<<dim3(768 / 64, M_ROWS / 128), 256>>>(
        h, w_qkv, b_qkv, nullptr, qkv, M_ROWS, 256, 768);
    // 3) RoPE + transpose
    rope_kernel<<<(Bb * Hh * Nn) / 8, 256>>>(qkv, fc, fs, qb, kb, vh);
    // 4) attention (64-row q-tiles, 4 warps)
    attn_mma_kernel<<<dim3(Nn / 64, Bb * Hh), 128>>>(qb, kb, vh, attn);
    // 5) proj + residual
    gemm_tc<false, true><<<dim3(256 / 64, M_ROWS / 128), 256>>>(
        attn, w_proj, b_proj, x, x2, M_ROWS, 256, 256);
    // 6) LN2
    ln_kernel<<<M_ROWS / 8, 256>>>(x2, ln2g, ln2b, h);
    // 7) FFN1 + relu
    gemm_tc<true, false><<<dim3(512 / 64, M_ROWS / 128), 256>>>(
        h, w1, b1, nullptr, t, M_ROWS, 256, 512);
    // 8) FFN2 + residual
    gemm_tc<false, true><<<dim3(256 / 64, M_ROWS / 128), 256>>>(
        t, w2, b2, x2, out, M_ROWS, 512, 256);
}

// round 10
// speedup vs baseline: 1.1011x; 1.1011x over previous
#include <cuda_runtime.h>
#include <cuda_bf16.h>
#include <cuda_fp16.h>
#include <math.h>
#include <stddef.h>
#include <stdint.h>

// Problem constants
#define Bb 4
#define Nn 2048
#define Dd 256
#define Hh 8
#define dhd 32
#define M_ROWS (Bb * Nn)            // 8192
#define EPSc 1e-5f
#define SCALEc 0.17677669529663687f // 1/sqrt(32)
#define SC2 (0.17677669529663687f * 1.4426950408889634f) // scale * log2(e)

// ---------------- scratch (device globals; no allocation allowed) ----------
__device__ float g_h[M_ROWS * Dd];
__device__ float g_qkv[M_ROWS * 3 * Dd];
__device__ __nv_bfloat16 g_qb[Bb * Hh * Nn * dhd];  // q * SC2, bf16
__device__ __nv_bfloat16 g_kb[Bb * Hh * Nn * dhd];
__device__ __half g_vh[Bb * Hh * Nn * dhd];         // v, f16
__device__ float g_attn[M_ROWS * Dd];
__device__ float g_x2[M_ROWS * Dd];
__device__ float g_t[M_ROWS * 2 * Dd];

// ---------------- mma helpers ----------------------------------------------
__device__ __forceinline__ void mma16816(float* c, const uint32_t* a,
                                         const uint32_t* b) {
    asm volatile(
        "mma.sync.aligned.m16n8k16.row.col.f32.bf16.bf16.f32 "
        "{%0,%1,%2,%3}, {%4,%5,%6,%7}, {%8,%9}, {%0,%1,%2,%3};"
        : "+f"(c[0]), "+f"(c[1]), "+f"(c[2]), "+f"(c[3])
        : "r"(a[0]), "r"(a[1]), "r"(a[2]), "r"(a[3]), "r"(b[0]), "r"(b[1]));
}
__device__ __forceinline__ void mma16816h(float* c, const uint32_t* a,
                                          const uint32_t* b) {
    asm volatile(
        "mma.sync.aligned.m16n8k16.row.col.f32.f16.f16.f32 "
        "{%0,%1,%2,%3}, {%4,%5,%6,%7}, {%8,%9}, {%0,%1,%2,%3};"
        : "+f"(c[0]), "+f"(c[1]), "+f"(c[2]), "+f"(c[3])
        : "r"(a[0]), "r"(a[1]), "r"(a[2]), "r"(a[3]), "r"(b[0]), "r"(b[1]));
}
__device__ __forceinline__ void mma_tf32(float* c, const uint32_t* a,
                                         const uint32_t* b) {
    asm volatile(
        "mma.sync.aligned.m16n8k8.row.col.f32.tf32.tf32.f32 "
        "{%0,%1,%2,%3}, {%4,%5,%6,%7}, {%8,%9}, {%0,%1,%2,%3};"
        : "+f"(c[0]), "+f"(c[1]), "+f"(c[2]), "+f"(c[3])
        : "r"(a[0]), "r"(a[1]), "r"(a[2]), "r"(a[3]), "r"(b[0]), "r"(b[1]));
}
__device__ __forceinline__ uint32_t f2tf32(float f) {
    uint32_t r;
    asm("cvt.rna.tf32.f32 %0, %1;" : "=r"(r) : "f"(f));
    return r;
}

// ---------------- LayerNorm -------------------------------------------------
__global__ void __launch_bounds__(256) ln_kernel(const float* __restrict__ x,
                                                 const float* __restrict__ g,
                                                 const float* __restrict__ b,
                                                 float* __restrict__ out) {
    int row = blockIdx.x * 8 + (threadIdx.x >> 5);
    int lane = threadIdx.x & 31;
    const float4* xr = (const float4*)(x + (size_t)row * Dd);
    float4 v0 = xr[lane];
    float4 v1 = xr[lane + 32];
    float s = v0.x + v0.y + v0.z + v0.w + v1.x + v1.y + v1.z + v1.w;
#pragma unroll
    for (int o = 16; o; o >>= 1) s += __shfl_xor_sync(0xffffffffu, s, o);
    float mu = s * (1.0f / Dd);
    float a0 = v0.x - mu, a1 = v0.y - mu, a2 = v0.z - mu, a3 = v0.w - mu;
    float a4 = v1.x - mu, a5 = v1.y - mu, a6 = v1.z - mu, a7 = v1.w - mu;
    float ss = a0 * a0 + a1 * a1 + a2 * a2 + a3 * a3 + a4 * a4 + a5 * a5 +
               a6 * a6 + a7 * a7;
#pragma unroll
    for (int o = 16; o; o >>= 1) ss += __shfl_xor_sync(0xffffffffu, ss, o);
    float inv = rsqrtf(ss * (1.0f / Dd) + EPSc);
    const float4* g4 = (const float4*)g;
    const float4* b4 = (const float4*)b;
    float4 g0 = g4[lane], g1 = g4[lane + 32];
    float4 bb0 = b4[lane], bb1 = b4[lane + 32];
    float4* o4 = (float4*)(out + (size_t)row * Dd);
    o4[lane] = make_float4(a0 * inv * g0.x + bb0.x, a1 * inv * g0.y + bb0.y,
                           a2 * inv * g0.z + bb0.z, a3 * inv * g0.w + bb0.w);
    o4[lane + 32] = make_float4(a4 * inv * g1.x + bb1.x, a5 * inv * g1.y + bb1.y,
                                a6 * inv * g1.z + bb1.z, a7 * inv * g1.w + bb1.w);
}

// ---------------- tf32 tensor-core GEMM with register prefetch --------------
// Block tile 128Mx64N, BK=32, 256 thr (8 warps 4x2), warp tile 32x32.
template <bool RELU, bool RES>
__global__ void __launch_bounds__(256) gemm_tc(const float* __restrict__ A,
                                               const float* __restrict__ W,
                                               const float* __restrict__ bias,
                                               const float* __restrict__ res,
                                               float* __restrict__ C,
                                               int M, int K, int Nc) {
    __shared__ uint32_t As[128][36];
    __shared__ uint32_t Ws[32][68];
    int tid = threadIdx.x;
    int w = tid >> 5, lane = tid & 31;
    int g = lane >> 2, t = lane & 3;
    int wm = (w & 3) * 32, wn = (w >> 2) * 32;
    int row0 = blockIdx.y * 128, col0 = blockIdx.x * 64;

    float c[2][4][4] = {};

    int arow = tid >> 1, acol = (tid & 1) * 16;
    int wrow = tid >> 3, wcol = (tid & 7) * 8;
    const float* apg = A + (size_t)(row0 + arow) * K + acol;
    const float* wpg = W + (size_t)wrow * Nc + col0 + wcol;

    // prefetch first tile into registers
    float4 aR[4], wR[2];
#pragma unroll
    for (int j = 0; j < 4; j++) aR[j] = *(const float4*)(apg + j * 4);
#pragma unroll
    for (int j = 0; j < 2; j++) wR[j] = *(const float4*)(wpg + j * 4);

    for (int k0 = 0; k0 < K; k0 += 32) {
        // stage current tile (cvt to tf32)
#pragma unroll
        for (int j = 0; j < 4; j++) {
            As[arow][acol + j * 4 + 0] = f2tf32(aR[j].x);
            As[arow][acol + j * 4 + 1] = f2tf32(aR[j].y);
            As[arow][acol + j * 4 + 2] = f2tf32(aR[j].z);
            As[arow][acol + j * 4 + 3] = f2tf32(aR[j].w);
        }
#pragma unroll
        for (int j = 0; j < 2; j++) {
            Ws[wrow][wcol + j * 4 + 0] = f2tf32(wR[j].x);
            Ws[wrow][wcol + j * 4 + 1] = f2tf32(wR[j].y);
            Ws[wrow][wcol + j * 4 + 2] = f2tf32(wR[j].z);
            Ws[wrow][wcol + j * 4 + 3] = f2tf32(wR[j].w);
        }
        __syncthreads();
        // prefetch next tile (hidden behind compute)
        if (k0 + 32 < K) {
#pragma unroll
            for (int j = 0; j < 4; j++)
                aR[j] = *(const float4*)(apg + k0 + 32 + j * 4);
#pragma unroll
            for (int j = 0; j < 2; j++)
                wR[j] = *(const float4*)(wpg + (size_t)(k0 + 32) * Nc + j * 4);
        }
#pragma unroll
        for (int kb = 0; kb < 32; kb += 8) {
            uint32_t a[2][4], b[4][2];
#pragma unroll
            for (int i = 0; i < 2; i++) {
                a[i][0] = As[wm + i * 16 + g][kb + t];
                a[i][1] = As[wm + i * 16 + g + 8][kb + t];
                a[i][2] = As[wm + i * 16 + g][kb + t + 4];
                a[i][3] = As[wm + i * 16 + g + 8][kb + t + 4];
            }
#pragma unroll
            for (int j = 0; j < 4; j++) {
                b[j][0] = Ws[kb + t][wn + j * 8 + g];
                b[j][1] = Ws[kb + t + 4][wn + j * 8 + g];
            }
#pragma unroll
            for (int i = 0; i < 2; i++)
#pragma unroll
                for (int j = 0; j < 4; j++) mma_tf32(c[i][j], a[i], b[j]);
        }
        __syncthreads();
    }

#pragma unroll
    for (int i = 0; i < 2; i++) {
        int r = row0 + wm + i * 16 + g;
#pragma unroll
        for (int j = 0; j < 4; j++) {
            int cc = col0 + wn + j * 8 + 2 * t;
            float2 bv = *(const float2*)(bias + cc);
            float v0 = c[i][j][0] + bv.x, v1 = c[i][j][1] + bv.y;
            float v2 = c[i][j][2] + bv.x, v3 = c[i][j][3] + bv.y;
            if (RELU) {
                v0 = fmaxf(v0, 0.f); v1 = fmaxf(v1, 0.f);
                v2 = fmaxf(v2, 0.f); v3 = fmaxf(v3, 0.f);
            }
            if (RES) {
                float2 r0 = *(const float2*)(res + (size_t)r * Nc + cc);
                float2 r1 = *(const float2*)(res + (size_t)(r + 8) * Nc + cc);
                v0 += r0.x; v1 += r0.y; v2 += r1.x; v3 += r1.y;
            }
            *(float2*)(C + (size_t)r * Nc + cc) = make_float2(v0, v1);
            *(float2*)(C + (size_t)(r + 8) * Nc + cc) = make_float2(v2, v3);
        }
    }
}

// ---------------- RoPE + transpose: q*SC2 bf16, k bf16, v f16 ---------------
__global__ void __launch_bounds__(256) rope_kernel(const float* __restrict__ qkv,
                                                   const float* __restrict__ fc,
                                                   const float* __restrict__ fs,
                                                   __nv_bfloat16* __restrict__ q,
                                                   __nv_bfloat16* __restrict__ k,
                                                   __half* __restrict__ v) {
    int row = blockIdx.x * 8 + (threadIdx.x >> 5);  // (b*H + h)*N + n
    int lane = threadIdx.x & 31;
    int n = row & (Nn - 1);
    int h = (row >> 11) & (Hh - 1);
    int b = row >> 14;
    const float* src = qkv + ((size_t)(b * Nn + n)) * (3 * Dd) + h * dhd;
    size_t obase = (size_t)row * dhd;
    if (lane < 16) {
        float c = fc[n * 16 + lane];
        float sn = fs[n * 16 + lane];
        float qe = src[2 * lane], qo = src[2 * lane + 1];
        q[obase + 2 * lane] = __float2bfloat16((qe * c - qo * sn) * SC2);
        q[obase + 2 * lane + 1] = __float2bfloat16((qe * sn + qo * c) * SC2);
        float ke = src[256 + 2 * lane], ko = src[256 + 2 * lane + 1];
        k[obase + 2 * lane] = __float2bfloat16(ke * c - ko * sn);
        k[obase + 2 * lane + 1] = __float2bfloat16(ke * sn + ko * c);
    }
    v[obase + lane] = __float2half(src[512 + lane]);
}

// ---------------- FA2 flash attention: 256 thr, 128 q-rows ------------------
// bf16 QK MMA, f16 exp2 + f16 PV, row-sum via ones-column MMA.
// K/V tiles register-prefetched: LDG for tile i+1 issued under tile i compute.
__global__ void __launch_bounds__(256) attn_mma_kernel(
    const __nv_bfloat16* __restrict__ Q,
    const __nv_bfloat16* __restrict__ K,
    const __half* __restrict__ V,
    float* __restrict__ Out) {
    __shared__ __nv_bfloat16 Ks[64][40];
    __shared__ __half Vt[32][72];

    int tid = threadIdx.x;
    int w = tid >> 5;
    int lane = tid & 31;
    int g = lane >> 2;
    int t = lane & 3;
    int bh = blockIdx.y;
    int q0 = blockIdx.x * 128;

    const __nv_bfloat16* Kb = K + (size_t)bh * Nn * dhd;
    const __half* Vb = V + (size_t)bh * Nn * dhd;

    int qrow = q0 + w * 16 + g;
    const __nv_bfloat16* Qr0 = Q + ((size_t)bh * Nn + qrow) * dhd;
    const __nv_bfloat16* Qr8 = Qr0 + 8 * dhd;
    uint32_t aQ[8];
#pragma unroll
    for (int ks = 0; ks < 2; ks++) {
        aQ[ks * 4 + 0] = *(const uint32_t*)(Qr0 + ks * 16 + 2 * t);
        aQ[ks * 4 + 1] = *(const uint32_t*)(Qr8 + ks * 16 + 2 * t);
        aQ[ks * 4 + 2] = *(const uint32_t*)(Qr0 + ks * 16 + 2 * t + 8);
        aQ[ks * 4 + 3] = *(const uint32_t*)(Qr8 + ks * 16 + 2 * t + 8);
    }

    float oacc[4][4] = {};
    float oL[4] = {};  // ones-column accumulator: row sums at t==0
    const uint32_t bONE = (g == 0) ? 0x3C003C00u : 0u;  // f16 ones col (n==0)
    uint32_t bL[2] = {bONE, bONE};

    // per-thread staging coords
    int krow = tid >> 2, kc = tid & 3;       // K: row, 16B chunk
    int vrow = tid >> 2, vq = tid & 3;       // V: row, 8-half chunk

    // prefetch first tile into registers
    uint4 kreg = *(const uint4*)(Kb + (size_t)krow * dhd + kc * 8);
    uint4 vreg = *(const uint4*)(Vb + (size_t)vrow * dhd + vq * 8);

    for (int t0 = 0; t0 < Nn; t0 += 64) {
        // stage K tile
        *(uint4*)(&Ks[krow][kc * 8]) = kreg;
        // stage V tile transposed: thread owns 8 halves of row vrow, d = vq*8..vq*8+7
        {
            const __half* vh = (const __half*)&vreg;
#pragma unroll
            for (int j = 0; j < 8; j++) Vt[vq * 8 + j][vrow] = vh[j];
        }
        __syncthreads();
        // prefetch next tile (hidden behind compute)
        if (t0 + 64 < Nn) {
            kreg = *(const uint4*)(Kb + (size_t)(t0 + 64 + krow) * dhd + kc * 8);
            vreg = *(const uint4*)(Vb + (size_t)(t0 + 64 + vrow) * dhd + vq * 8);
        }

        // S = Qsc K^T (bf16)
        float cS[8][4];
#pragma unroll
        for (int n = 0; n < 8; n++) {
            cS[n][0] = cS[n][1] = cS[n][2] = cS[n][3] = 0.f;
            const __nv_bfloat16* kr = &Ks[n * 8 + g][0];
#pragma unroll
            for (int ks = 0; ks < 2; ks++) {
                uint32_t b[2];
                b[0] = *(const uint32_t*)(kr + ks * 16 + 2 * t);
                b[1] = *(const uint32_t*)(kr + ks * 16 + 2 * t + 8);
                mma16816(cS[n], &aQ[ks * 4], b);
            }
        }

        // p = exp2(S) in f16x2 (S pre-scaled by SC2 via Q)
        uint32_t pf[8][2];
#pragma unroll
        for (int n = 0; n < 8; n++) {
            __half2 lo = h2exp2(__floats2half2_rn(cS[n][0], cS[n][1]));
            __half2 hi = h2exp2(__floats2half2_rn(cS[n][2], cS[n][3]));
            pf[n][0] = *(uint32_t*)&lo;
            pf[n][1] = *(uint32_t*)&hi;
        }

        // O += P V (f16), plus ones-column for row sums
#pragma unroll
        for (int kk = 0; kk < 4; kk++) {
            uint32_t aP[4] = {pf[2 * kk][0], pf[2 * kk][1],
                              pf[2 * kk + 1][0], pf[2 * kk + 1][1]};
#pragma unroll
            for (int nd = 0; nd < 4; nd++) {
                const __half* vr = &Vt[nd * 8 + g][0];
                uint32_t b[2];
                b[0] = *(const uint32_t*)(vr + kk * 16 + 2 * t);
                b[1] = *(const uint32_t*)(vr + kk * 16 + 2 * t + 8);
                mma16816h(oacc[nd], aP, b);
            }
            mma16816h(oL, aP, bL);
        }
        __syncthreads();
    }

    // broadcast row sums from t==0 lane of each group
    float l0 = __shfl_sync(0xffffffffu, oL[0], lane & 28);
    float l1 = __shfl_sync(0xffffffffu, oL[2], lane & 28);
    float inv0 = 1.0f / l0;
    float inv1 = 1.0f / l1;

    int b = bh >> 3, h = bh & 7;
    size_t base0 = ((size_t)(b * Nn + qrow)) * Dd + h * dhd;
    size_t base1 = base0 + 8 * Dd;
#pragma unroll
    for (int nd = 0; nd < 4; nd++) {
        int col = nd * 8 + 2 * t;
        *(float2*)(Out + base0 + col) =
            make_float2(oacc[nd][0] * inv0, oacc[nd][1] * inv0);
        *(float2*)(Out + base1 + col) =
            make_float2(oacc[nd][2] * inv1, oacc[nd][3] * inv1);
    }
}

// ---------------- launch ---------------------------------------------------
extern "C" void kernel_launch(void* const* d_in, const int* in_sizes, int n_in,
                              void* d_out, int out_size) {
    const float* x      = (const float*)d_in[0];
    const float* fc     = (const float*)d_in[1];
    const float* fs     = (const float*)d_in[2];
    const float* w_qkv  = (const float*)d_in[3];
    const float* b_qkv  = (const float*)d_in[4];
    const float* w_proj = (const float*)d_in[5];
    const float* b_proj = (const float*)d_in[6];
    const float* ln1g   = (const float*)d_in[7];
    const float* ln1b   = (const float*)d_in[8];
    const float* ln2g   = (const float*)d_in[9];
    const float* ln2b   = (const float*)d_in[10];
    const float* w1     = (const float*)d_in[11];
    const float* b1     = (const float*)d_in[12];
    const float* w2     = (const float*)d_in[13];
    const float* b2     = (const float*)d_in[14];
    float* out = (float*)d_out;

    float *h, *qkv, *attn, *x2, *t;
    __nv_bfloat16 *qb, *kb;
    __half *vh;
    cudaGetSymbolAddress((void**)&h, g_h);
    cudaGetSymbolAddress((void**)&qkv, g_qkv);
    cudaGetSymbolAddress((void**)&qb, g_qb);
    cudaGetSymbolAddress((void**)&kb, g_kb);
    cudaGetSymbolAddress((void**)&vh, g_vh);
    cudaGetSymbolAddress((void**)&attn, g_attn);
    cudaGetSymbolAddress((void**)&x2, g_x2);
    cudaGetSymbolAddress((void**)&t, g_t);

    // 1) LN1
    ln_kernel<<<M_ROWS / 8, 256>>>(x, ln1g, ln1b, h);
    // 2) QKV gemm (tf32 TC)
    gemm_tc<false, false><<<dim3(768 / 64, M_ROWS / 128), 256>>>(
        h, w_qkv, b_qkv, nullptr, qkv, M_ROWS, 256, 768);
    // 3) RoPE + transpose
    rope_kernel<<<(Bb * Hh * Nn) / 8, 256>>>(qkv, fc, fs, qb, kb, vh);
    // 4) attention (128-row q-tiles, 8 warps)
    attn_mma_kernel<<<dim3(Nn / 128, Bb * Hh), 256>>>(qb, kb, vh, attn);
    // 5) proj + residual
    gemm_tc<false, true><<<dim3(256 / 64, M_ROWS / 128), 256>>>(
        attn, w_proj, b_proj, x, x2, M_ROWS, 256, 256);
    // 6) LN2
    ln_kernel<<<M_ROWS / 8, 256>>>(x2, ln2g, ln2b, h);
    // 7) FFN1 + relu
    gemm_tc<true, false><<<dim3(512 / 64, M_ROWS / 128), 256>>>(
        h, w1, b1, nullptr, t, M_ROWS, 256, 512);
    // 8) FFN2 + residual
    gemm_tc<false, true><<<dim3(256 / 64, M_ROWS / 128), 256>>>(
        t, w2, b2, x2, out, M_ROWS, 512, 256);
}

// round 13
// speedup vs baseline: 1.1280x; 1.0244x over previous
#include <cuda_runtime.h>
#include <cuda_bf16.h>
#include <cuda_fp16.h>
#include <math.h>
#include <stddef.h>
#include <stdint.h>

// Problem constants
#define Bb 4
#define Nn 2048
#define Dd 256
#define Hh 8
#define dhd 32
#define M_ROWS (Bb * Nn)            // 8192
#define EPSc 1e-5f
#define SCALEc 0.17677669529663687f // 1/sqrt(32)
#define SC2 (0.17677669529663687f * 1.4426950408889634f) // scale * log2(e)

// gemm_tc dynamic smem: double-buffered As[128][36] + Ws[32][72] (tf32 bits)
#define GEMM_SMEM_BYTES (2 * (128 * 36 + 32 * 72) * 4)  // 55296

// ---------------- scratch (device globals; no allocation allowed) ----------
__device__ float g_h[M_ROWS * Dd];
__device__ float g_qkv[M_ROWS * 3 * Dd];
__device__ __nv_bfloat16 g_qb[Bb * Hh * Nn * dhd];  // q * SC2, bf16
__device__ __nv_bfloat16 g_kb[Bb * Hh * Nn * dhd];
__device__ __half g_vh[Bb * Hh * Nn * dhd];         // v, f16
__device__ float g_attn[M_ROWS * Dd];
__device__ float g_x2[M_ROWS * Dd];
__device__ float g_t[M_ROWS * 2 * Dd];

// ---------------- mma helpers ----------------------------------------------
__device__ __forceinline__ void mma16816(float* c, const uint32_t* a,
                                         const uint32_t* b) {
    asm volatile(
        "mma.sync.aligned.m16n8k16.row.col.f32.bf16.bf16.f32 "
        "{%0,%1,%2,%3}, {%4,%5,%6,%7}, {%8,%9}, {%0,%1,%2,%3};"
        : "+f"(c[0]), "+f"(c[1]), "+f"(c[2]), "+f"(c[3])
        : "r"(a[0]), "r"(a[1]), "r"(a[2]), "r"(a[3]), "r"(b[0]), "r"(b[1]));
}
__device__ __forceinline__ void mma16816h(float* c, const uint32_t* a,
                                          const uint32_t* b) {
    asm volatile(
        "mma.sync.aligned.m16n8k16.row.col.f32.f16.f16.f32 "
        "{%0,%1,%2,%3}, {%4,%5,%6,%7}, {%8,%9}, {%0,%1,%2,%3};"
        : "+f"(c[0]), "+f"(c[1]), "+f"(c[2]), "+f"(c[3])
        : "r"(a[0]), "r"(a[1]), "r"(a[2]), "r"(a[3]), "r"(b[0]), "r"(b[1]));
}
__device__ __forceinline__ void mma_tf32(float* c, const uint32_t* a,
                                         const uint32_t* b) {
    asm volatile(
        "mma.sync.aligned.m16n8k8.row.col.f32.tf32.tf32.f32 "
        "{%0,%1,%2,%3}, {%4,%5,%6,%7}, {%8,%9}, {%0,%1,%2,%3};"
        : "+f"(c[0]), "+f"(c[1]), "+f"(c[2]), "+f"(c[3])
        : "r"(a[0]), "r"(a[1]), "r"(a[2]), "r"(a[3]), "r"(b[0]), "r"(b[1]));
}
__device__ __forceinline__ uint32_t f2tf32(float f) {
    uint32_t r;
    asm("cvt.rna.tf32.f32 %0, %1;" : "=r"(r) : "f"(f));
    return r;
}

// ---------------- LayerNorm -------------------------------------------------
__global__ void __launch_bounds__(256) ln_kernel(const float* __restrict__ x,
                                                 const float* __restrict__ g,
                                                 const float* __restrict__ b,
                                                 float* __restrict__ out) {
    int row = blockIdx.x * 8 + (threadIdx.x >> 5);
    int lane = threadIdx.x & 31;
    const float4* xr = (const float4*)(x + (size_t)row * Dd);
    float4 v0 = xr[lane];
    float4 v1 = xr[lane + 32];
    float s = v0.x + v0.y + v0.z + v0.w + v1.x + v1.y + v1.z + v1.w;
#pragma unroll
    for (int o = 16; o; o >>= 1) s += __shfl_xor_sync(0xffffffffu, s, o);
    float mu = s * (1.0f / Dd);
    float a0 = v0.x - mu, a1 = v0.y - mu, a2 = v0.z - mu, a3 = v0.w - mu;
    float a4 = v1.x - mu, a5 = v1.y - mu, a6 = v1.z - mu, a7 = v1.w - mu;
    float ss = a0 * a0 + a1 * a1 + a2 * a2 + a3 * a3 + a4 * a4 + a5 * a5 +
               a6 * a6 + a7 * a7;
#pragma unroll
    for (int o = 16; o; o >>= 1) ss += __shfl_xor_sync(0xffffffffu, ss, o);
    float inv = rsqrtf(ss * (1.0f / Dd) + EPSc);
    const float4* g4 = (const float4*)g;
    const float4* b4 = (const float4*)b;
    float4 g0 = g4[lane], g1 = g4[lane + 32];
    float4 bb0 = b4[lane], bb1 = b4[lane + 32];
    float4* o4 = (float4*)(out + (size_t)row * Dd);
    o4[lane] = make_float4(a0 * inv * g0.x + bb0.x, a1 * inv * g0.y + bb0.y,
                           a2 * inv * g0.z + bb0.z, a3 * inv * g0.w + bb0.w);
    o4[lane + 32] = make_float4(a4 * inv * g1.x + bb1.x, a5 * inv * g1.y + bb1.y,
                                a6 * inv * g1.z + bb1.z, a7 * inv * g1.w + bb1.w);
}

// ---------------- tf32 TC GEMM: double-buffered smem + reg prefetch ---------
// Block tile 128Mx64N, BK=32, 256 thr (8 warps 4x2), warp tile 32x32.
// Ws stride 72 (== 8 mod 32) -> conflict-free B-fragment LDS.
template <bool RELU, bool RES>
__global__ void __launch_bounds__(256) gemm_tc(const float* __restrict__ A,
                                               const float* __restrict__ W,
                                               const float* __restrict__ bias,
                                               const float* __restrict__ res,
                                               float* __restrict__ C,
                                               int M, int K, int Nc) {
    extern __shared__ uint32_t dsm[];
    uint32_t (*As)[128][36] = (uint32_t(*)[128][36])dsm;
    uint32_t (*Ws)[32][72] = (uint32_t(*)[32][72])(dsm + 2 * 128 * 36);

    int tid = threadIdx.x;
    int w = tid >> 5, lane = tid & 31;
    int g = lane >> 2, t = lane & 3;
    int wm = (w & 3) * 32, wn = (w >> 2) * 32;
    int row0 = blockIdx.y * 128, col0 = blockIdx.x * 64;

    float c[2][4][4] = {};

    int arow = tid >> 1, acol = (tid & 1) * 16;
    int wrow = tid >> 3, wcol = (tid & 7) * 8;
    const float* apg = A + (size_t)(row0 + arow) * K + acol;
    const float* wpg = W + (size_t)wrow * Nc + col0 + wcol;

    // load + stage tile 0
    float4 aR[4], wR[2];
#pragma unroll
    for (int j = 0; j < 4; j++) aR[j] = *(const float4*)(apg + j * 4);
#pragma unroll
    for (int j = 0; j < 2; j++) wR[j] = *(const float4*)(wpg + j * 4);
#pragma unroll
    for (int j = 0; j < 4; j++) {
        As[0][arow][acol + j * 4 + 0] = f2tf32(aR[j].x);
        As[0][arow][acol + j * 4 + 1] = f2tf32(aR[j].y);
        As[0][arow][acol + j * 4 + 2] = f2tf32(aR[j].z);
        As[0][arow][acol + j * 4 + 3] = f2tf32(aR[j].w);
    }
#pragma unroll
    for (int j = 0; j < 2; j++) {
        uint4 p = make_uint4(f2tf32(wR[j].x), f2tf32(wR[j].y),
                             f2tf32(wR[j].z), f2tf32(wR[j].w));
        *(uint4*)(&Ws[0][wrow][wcol + j * 4]) = p;
    }
    __syncthreads();

    int nIter = K >> 5;
    for (int it = 0; it < nIter; it++) {
        int buf = it & 1;
        // issue LDG for next tile (latency hidden behind compute)
        if (it + 1 < nIter) {
            int k0 = (it + 1) << 5;
#pragma unroll
            for (int j = 0; j < 4; j++)
                aR[j] = *(const float4*)(apg + k0 + j * 4);
#pragma unroll
            for (int j = 0; j < 2; j++)
                wR[j] = *(const float4*)(wpg + (size_t)k0 * Nc + j * 4);
        }
        // compute from buf
#pragma unroll
        for (int kb = 0; kb < 32; kb += 8) {
            uint32_t a[2][4], b[4][2];
#pragma unroll
            for (int i = 0; i < 2; i++) {
                a[i][0] = As[buf][wm + i * 16 + g][kb + t];
                a[i][1] = As[buf][wm + i * 16 + g + 8][kb + t];
                a[i][2] = As[buf][wm + i * 16 + g][kb + t + 4];
                a[i][3] = As[buf][wm + i * 16 + g + 8][kb + t + 4];
            }
#pragma unroll
            for (int j = 0; j < 4; j++) {
                b[j][0] = Ws[buf][kb + t][wn + j * 8 + g];
                b[j][1] = Ws[buf][kb + t + 4][wn + j * 8 + g];
            }
#pragma unroll
            for (int i = 0; i < 2; i++)
#pragma unroll
                for (int j = 0; j < 4; j++) mma_tf32(c[i][j], a[i], b[j]);
        }
        // stage next tile into the other buffer (overlaps other warps' MMA)
        if (it + 1 < nIter) {
            int nb = buf ^ 1;
#pragma unroll
            for (int j = 0; j < 4; j++) {
                As[nb][arow][acol + j * 4 + 0] = f2tf32(aR[j].x);
                As[nb][arow][acol + j * 4 + 1] = f2tf32(aR[j].y);
                As[nb][arow][acol + j * 4 + 2] = f2tf32(aR[j].z);
                As[nb][arow][acol + j * 4 + 3] = f2tf32(aR[j].w);
            }
#pragma unroll
            for (int j = 0; j < 2; j++) {
                uint4 p = make_uint4(f2tf32(wR[j].x), f2tf32(wR[j].y),
                                     f2tf32(wR[j].z), f2tf32(wR[j].w));
                *(uint4*)(&Ws[nb][wrow][wcol + j * 4]) = p;
            }
        }
        __syncthreads();
    }

    // epilogue: bias (+relu) (+residual), fp32 out
#pragma unroll
    for (int i = 0; i < 2; i++) {
        int r = row0 + wm + i * 16 + g;
#pragma unroll
        for (int j = 0; j < 4; j++) {
            int cc = col0 + wn + j * 8 + 2 * t;
            float2 bv = *(const float2*)(bias + cc);
            float v0 = c[i][j][0] + bv.x, v1 = c[i][j][1] + bv.y;
            float v2 = c[i][j][2] + bv.x, v3 = c[i][j][3] + bv.y;
            if (RELU) {
                v0 = fmaxf(v0, 0.f); v1 = fmaxf(v1, 0.f);
                v2 = fmaxf(v2, 0.f); v3 = fmaxf(v3, 0.f);
            }
            if (RES) {
                float2 r0 = *(const float2*)(res + (size_t)r * Nc + cc);
                float2 r1 = *(const float2*)(res + (size_t)(r + 8) * Nc + cc);
                v0 += r0.x; v1 += r0.y; v2 += r1.x; v3 += r1.y;
            }
            *(float2*)(C + (size_t)r * Nc + cc) = make_float2(v0, v1);
            *(float2*)(C + (size_t)(r + 8) * Nc + cc) = make_float2(v2, v3);
        }
    }
}

// ---------------- RoPE + transpose: q*SC2 bf16, k bf16, v f16 ---------------
__global__ void __launch_bounds__(256) rope_kernel(const float* __restrict__ qkv,
                                                   const float* __restrict__ fc,
                                                   const float* __restrict__ fs,
                                                   __nv_bfloat16* __restrict__ q,
                                                   __nv_bfloat16* __restrict__ k,
                                                   __half* __restrict__ v) {
    int row = blockIdx.x * 8 + (threadIdx.x >> 5);  // (b*H + h)*N + n
    int lane = threadIdx.x & 31;
    int n = row & (Nn - 1);
    int h = (row >> 11) & (Hh - 1);
    int b = row >> 14;
    const float* src = qkv + ((size_t)(b * Nn + n)) * (3 * Dd) + h * dhd;
    size_t obase = (size_t)row * dhd;
    if (lane < 16) {
        float c = fc[n * 16 + lane];
        float sn = fs[n * 16 + lane];
        float qe = src[2 * lane], qo = src[2 * lane + 1];
        q[obase + 2 * lane] = __float2bfloat16((qe * c - qo * sn) * SC2);
        q[obase + 2 * lane + 1] = __float2bfloat16((qe * sn + qo * c) * SC2);
        float ke = src[256 + 2 * lane], ko = src[256 + 2 * lane + 1];
        k[obase + 2 * lane] = __float2bfloat16(ke * c - ko * sn);
        k[obase + 2 * lane + 1] = __float2bfloat16(ke * sn + ko * c);
    }
    v[obase + lane] = __float2half(src[512 + lane]);
}

// ---------------- FA2 flash attention: 256 thr, 128 q-rows ------------------
// bf16 QK MMA, f16 exp2 + f16 PV, row-sum via ones-column MMA.
// K/V tiles register-prefetched.
__global__ void __launch_bounds__(256) attn_mma_kernel(
    const __nv_bfloat16* __restrict__ Q,
    const __nv_bfloat16* __restrict__ K,
    const __half* __restrict__ V,
    float* __restrict__ Out) {
    __shared__ __nv_bfloat16 Ks[64][40];
    __shared__ __half Vt[32][72];

    int tid = threadIdx.x;
    int w = tid >> 5;
    int lane = tid & 31;
    int g = lane >> 2;
    int t = lane & 3;
    int bh = blockIdx.y;
    int q0 = blockIdx.x * 128;

    const __nv_bfloat16* Kb = K + (size_t)bh * Nn * dhd;
    const __half* Vb = V + (size_t)bh * Nn * dhd;

    int qrow = q0 + w * 16 + g;
    const __nv_bfloat16* Qr0 = Q + ((size_t)bh * Nn + qrow) * dhd;
    const __nv_bfloat16* Qr8 = Qr0 + 8 * dhd;
    uint32_t aQ[8];
#pragma unroll
    for (int ks = 0; ks < 2; ks++) {
        aQ[ks * 4 + 0] = *(const uint32_t*)(Qr0 + ks * 16 + 2 * t);
        aQ[ks * 4 + 1] = *(const uint32_t*)(Qr8 + ks * 16 + 2 * t);
        aQ[ks * 4 + 2] = *(const uint32_t*)(Qr0 + ks * 16 + 2 * t + 8);
        aQ[ks * 4 + 3] = *(const uint32_t*)(Qr8 + ks * 16 + 2 * t + 8);
    }

    float oacc[4][4] = {};
    float oL[4] = {};  // ones-column accumulator: row sums at t==0
    const uint32_t bONE = (g == 0) ? 0x3C003C00u : 0u;  // f16 ones col (n==0)
    uint32_t bL[2] = {bONE, bONE};

    // per-thread staging coords
    int krow = tid >> 2, kc = tid & 3;       // K: row, 16B chunk
    int vrow = tid >> 2, vq = tid & 3;       // V: row, 8-half chunk

    // prefetch first tile into registers
    uint4 kreg = *(const uint4*)(Kb + (size_t)krow * dhd + kc * 8);
    uint4 vreg = *(const uint4*)(Vb + (size_t)vrow * dhd + vq * 8);

    for (int t0 = 0; t0 < Nn; t0 += 64) {
        // stage K tile
        *(uint4*)(&Ks[krow][kc * 8]) = kreg;
        // stage V tile transposed
        {
            const __half* vh = (const __half*)&vreg;
#pragma unroll
            for (int j = 0; j < 8; j++) Vt[vq * 8 + j][vrow] = vh[j];
        }
        __syncthreads();
        // prefetch next tile (hidden behind compute)
        if (t0 + 64 < Nn) {
            kreg = *(const uint4*)(Kb + (size_t)(t0 + 64 + krow) * dhd + kc * 8);
            vreg = *(const uint4*)(Vb + (size_t)(t0 + 64 + vrow) * dhd + vq * 8);
        }

        // S = Qsc K^T (bf16)
        float cS[8][4];
#pragma unroll
        for (int n = 0; n < 8; n++) {
            cS[n][0] = cS[n][1] = cS[n][2] = cS[n][3] = 0.f;
            const __nv_bfloat16* kr = &Ks[n * 8 + g][0];
#pragma unroll
            for (int ks = 0; ks < 2; ks++) {
                uint32_t b[2];
                b[0] = *(const uint32_t*)(kr + ks * 16 + 2 * t);
                b[1] = *(const uint32_t*)(kr + ks * 16 + 2 * t + 8);
                mma16816(cS[n], &aQ[ks * 4], b);
            }
        }

        // p = exp2(S) in f16x2 (S pre-scaled by SC2 via Q)
        uint32_t pf[8][2];
#pragma unroll
        for (int n = 0; n < 8; n++) {
            __half2 lo = h2exp2(__floats2half2_rn(cS[n][0], cS[n][1]));
            __half2 hi = h2exp2(__floats2half2_rn(cS[n][2], cS[n][3]));
            pf[n][0] = *(uint32_t*)&lo;
            pf[n][1] = *(uint32_t*)&hi;
        }

        // O += P V (f16), plus ones-column for row sums
#pragma unroll
        for (int kk = 0; kk < 4; kk++) {
            uint32_t aP[4] = {pf[2 * kk][0], pf[2 * kk][1],
                              pf[2 * kk + 1][0], pf[2 * kk + 1][1]};
#pragma unroll
            for (int nd = 0; nd < 4; nd++) {
                const __half* vr = &Vt[nd * 8 + g][0];
                uint32_t b[2];
                b[0] = *(const uint32_t*)(vr + kk * 16 + 2 * t);
                b[1] = *(const uint32_t*)(vr + kk * 16 + 2 * t + 8);
                mma16816h(oacc[nd], aP, b);
            }
            mma16816h(oL, aP, bL);
        }
        __syncthreads();
    }

    // broadcast row sums from t==0 lane of each group
    float l0 = __shfl_sync(0xffffffffu, oL[0], lane & 28);
    float l1 = __shfl_sync(0xffffffffu, oL[2], lane & 28);
    float inv0 = 1.0f / l0;
    float inv1 = 1.0f / l1;

    int b = bh >> 3, h = bh & 7;
    size_t base0 = ((size_t)(b * Nn + qrow)) * Dd + h * dhd;
    size_t base1 = base0 + 8 * Dd;
#pragma unroll
    for (int nd = 0; nd < 4; nd++) {
        int col = nd * 8 + 2 * t;
        *(float2*)(Out + base0 + col) =
            make_float2(oacc[nd][0] * inv0, oacc[nd][1] * inv0);
        *(float2*)(Out + base1 + col) =
            make_float2(oacc[nd][2] * inv1, oacc[nd][3] * inv1);
    }
}

// ---------------- launch ---------------------------------------------------
extern "C" void kernel_launch(void* const* d_in, const int* in_sizes, int n_in,
                              void* d_out, int out_size) {
    const float* x      = (const float*)d_in[0];
    const float* fc     = (const float*)d_in[1];
    const float* fs     = (const float*)d_in[2];
    const float* w_qkv  = (const float*)d_in[3];
    const float* b_qkv  = (const float*)d_in[4];
    const float* w_proj = (const float*)d_in[5];
    const float* b_proj = (const float*)d_in[6];
    const float* ln1g   = (const float*)d_in[7];
    const float* ln1b   = (const float*)d_in[8];
    const float* ln2g   = (const float*)d_in[9];
    const float* ln2b   = (const float*)d_in[10];
    const float* w1     = (const float*)d_in[11];
    const float* b1     = (const float*)d_in[12];
    const float* w2     = (const float*)d_in[13];
    const float* b2     = (const float*)d_in[14];
    float* out = (float*)d_out;

    float *h, *qkv, *attn, *x2, *t;
    __nv_bfloat16 *qb, *kb;
    __half *vh;
    cudaGetSymbolAddress((void**)&h, g_h);
    cudaGetSymbolAddress((void**)&qkv, g_qkv);
    cudaGetSymbolAddress((void**)&qb, g_qb);
    cudaGetSymbolAddress((void**)&kb, g_kb);
    cudaGetSymbolAddress((void**)&vh, g_vh);
    cudaGetSymbolAddress((void**)&attn, g_attn);
    cudaGetSymbolAddress((void**)&x2, g_x2);
    cudaGetSymbolAddress((void**)&t, g_t);

    // opt-in dynamic smem for gemm_tc (idempotent)
    cudaFuncSetAttribute(gemm_tc<false, false>,
                         cudaFuncAttributeMaxDynamicSharedMemorySize,
                         GEMM_SMEM_BYTES);
    cudaFuncSetAttribute(gemm_tc<false, true>,
                         cudaFuncAttributeMaxDynamicSharedMemorySize,
                         GEMM_SMEM_BYTES);
    cudaFuncSetAttribute(gemm_tc<true, false>,
                         cudaFuncAttributeMaxDynamicSharedMemorySize,
                         GEMM_SMEM_BYTES);

    // 1) LN1
    ln_kernel<<<M_ROWS / 8, 256>>>(x, ln1g, ln1b, h);
    // 2) QKV gemm (tf32 TC)
    gemm_tc<false, false><<<dim3(768 / 64, M_ROWS / 128), 256, GEMM_SMEM_BYTES>>>(
        h, w_qkv, b_qkv, nullptr, qkv, M_ROWS, 256, 768);
    // 3) RoPE + transpose
    rope_kernel<<<(Bb * Hh * Nn) / 8, 256>>>(qkv, fc, fs, qb, kb, vh);
    // 4) attention (128-row q-tiles, 8 warps)
    attn_mma_kernel<<<dim3(Nn / 128, Bb * Hh), 256>>>(qb, kb, vh, attn);
    // 5) proj + residual
    gemm_tc<false, true><<<dim3(256 / 64, M_ROWS / 128), 256, GEMM_SMEM_BYTES>>>(
        attn, w_proj, b_proj, x, x2, M_ROWS, 256, 256);
    // 6) LN2
    ln_kernel<<<M_ROWS / 8, 256>>>(x2, ln2g, ln2b, h);
    // 7) FFN1 + relu
    gemm_tc<true, false><<<dim3(512 / 64, M_ROWS / 128), 256, GEMM_SMEM_BYTES>>>(
        h, w1, b1, nullptr, t, M_ROWS, 256, 512);
    // 8) FFN2 + residual
    gemm_tc<false, true><<<dim3(256 / 64, M_ROWS / 128), 256, GEMM_SMEM_BYTES>>>(
        t, w2, b2, x2, out, M_ROWS, 512, 256);
}

// round 14
// speedup vs baseline: 1.3232x; 1.1731x over previous
#include <cuda_runtime.h>
#include <cuda_bf16.h>
#include <cuda_fp16.h>
#include <math.h>
#include <stddef.h>
#include <stdint.h>

// Problem constants
#define Bb 4
#define Nn 2048
#define Dd 256
#define Hh 8
#define dhd 32
#define M_ROWS (Bb * Nn)            // 8192
#define EPSc 1e-5f
#define SCALEc 0.17677669529663687f // 1/sqrt(32)
#define SC2 (0.17677669529663687f * 1.4426950408889634f) // scale * log2(e)

// ---------------- scratch (device globals; no allocation allowed) ----------
__device__ float g_h[M_ROWS * Dd];
__device__ float g_qkv[M_ROWS * 3 * Dd];
__device__ __nv_bfloat16 g_qb[Bb * Hh * Nn * dhd];  // q * SC2, bf16
__device__ __nv_bfloat16 g_kb[Bb * Hh * Nn * dhd];
__device__ __half g_vh[Bb * Hh * Nn * dhd];         // v, f16
__device__ float g_attn[M_ROWS * Dd];
__device__ float g_x2[M_ROWS * Dd];
__device__ float g_t[M_ROWS * 2 * Dd];

// ---------------- mma helpers ----------------------------------------------
__device__ __forceinline__ void mma16816(float* c, const uint32_t* a,
                                         const uint32_t* b) {
    asm volatile(
        "mma.sync.aligned.m16n8k16.row.col.f32.bf16.bf16.f32 "
        "{%0,%1,%2,%3}, {%4,%5,%6,%7}, {%8,%9}, {%0,%1,%2,%3};"
        : "+f"(c[0]), "+f"(c[1]), "+f"(c[2]), "+f"(c[3])
        : "r"(a[0]), "r"(a[1]), "r"(a[2]), "r"(a[3]), "r"(b[0]), "r"(b[1]));
}
__device__ __forceinline__ void mma16816h(float* c, const uint32_t* a,
                                          const uint32_t* b) {
    asm volatile(
        "mma.sync.aligned.m16n8k16.row.col.f32.f16.f16.f32 "
        "{%0,%1,%2,%3}, {%4,%5,%6,%7}, {%8,%9}, {%0,%1,%2,%3};"
        : "+f"(c[0]), "+f"(c[1]), "+f"(c[2]), "+f"(c[3])
        : "r"(a[0]), "r"(a[1]), "r"(a[2]), "r"(a[3]), "r"(b[0]), "r"(b[1]));
}
__device__ __forceinline__ uint32_t fp2bf2(float lo, float hi) {
    __nv_bfloat162 h = __floats2bfloat162_rn(lo, hi);
    return *(uint32_t*)&h;
}

// ---------------- LayerNorm -------------------------------------------------
__global__ void __launch_bounds__(256) ln_kernel(const float* __restrict__ x,
                                                 const float* __restrict__ g,
                                                 const float* __restrict__ b,
                                                 float* __restrict__ out) {
    int row = blockIdx.x * 8 + (threadIdx.x >> 5);
    int lane = threadIdx.x & 31;
    const float4* xr = (const float4*)(x + (size_t)row * Dd);
    float4 v0 = xr[lane];
    float4 v1 = xr[lane + 32];
    float s = v0.x + v0.y + v0.z + v0.w + v1.x + v1.y + v1.z + v1.w;
#pragma unroll
    for (int o = 16; o; o >>= 1) s += __shfl_xor_sync(0xffffffffu, s, o);
    float mu = s * (1.0f / Dd);
    float a0 = v0.x - mu, a1 = v0.y - mu, a2 = v0.z - mu, a3 = v0.w - mu;
    float a4 = v1.x - mu, a5 = v1.y - mu, a6 = v1.z - mu, a7 = v1.w - mu;
    float ss = a0 * a0 + a1 * a1 + a2 * a2 + a3 * a3 + a4 * a4 + a5 * a5 +
               a6 * a6 + a7 * a7;
#pragma unroll
    for (int o = 16; o; o >>= 1) ss += __shfl_xor_sync(0xffffffffu, ss, o);
    float inv = rsqrtf(ss * (1.0f / Dd) + EPSc);
    const float4* g4 = (const float4*)g;
    const float4* b4 = (const float4*)b;
    float4 g0 = g4[lane], g1 = g4[lane + 32];
    float4 bb0 = b4[lane], bb1 = b4[lane + 32];
    float4* o4 = (float4*)(out + (size_t)row * Dd);
    o4[lane] = make_float4(a0 * inv * g0.x + bb0.x, a1 * inv * g0.y + bb0.y,
                           a2 * inv * g0.z + bb0.z, a3 * inv * g0.w + bb0.w);
    o4[lane + 32] = make_float4(a4 * inv * g1.x + bb1.x, a5 * inv * g1.y + bb1.y,
                                a6 * inv * g1.z + bb1.z, a7 * inv * g1.w + bb1.w);
}

// ---------------- bf16 TC GEMM: double-buffered smem + reg prefetch ---------
// Block tile 128Mx64N, BK=32, 256 thr (8 warps 4x2), warp tile 32x32.
// A staged [m][k] stride 40 halves; W staged TRANSPOSED [n][k] stride 40
// (consecutive-k B fragments, same proven layout as attention Ks).
template <bool RELU, bool RES>
__global__ void __launch_bounds__(256) gemm_tc(const float* __restrict__ A,
                                               const float* __restrict__ W,
                                               const float* __restrict__ bias,
                                               const float* __restrict__ res,
                                               float* __restrict__ C,
                                               int M, int K, int Nc) {
    __shared__ __nv_bfloat16 As[2][128][40];
    __shared__ __nv_bfloat16 Ws[2][64][40];

    int tid = threadIdx.x;
    int w = tid >> 5, lane = tid & 31;
    int g = lane >> 2, t = lane & 3;
    int wm = (w & 3) * 32, wn = (w >> 2) * 32;
    int row0 = blockIdx.y * 128, col0 = blockIdx.x * 64;

    float c[2][4][4] = {};

    // A staging: thread owns 16 consecutive k at one row
    int arow = tid >> 1, acol = (tid & 1) * 16;
    const float* apg = A + (size_t)(row0 + arow) * K + acol;
    // W staging: thread owns 8 consecutive k at one n (coalesced across n)
    int wnc = tid & 63, wk = (tid >> 6) * 8;
    const float* wpg = W + (size_t)wk * Nc + col0 + wnc;

    // load tile 0
    float4 aR[4];
    float wF[8];
#pragma unroll
    for (int j = 0; j < 4; j++) aR[j] = *(const float4*)(apg + j * 4);
#pragma unroll
    for (int j = 0; j < 8; j++) wF[j] = wpg[(size_t)j * Nc];

    // stage tile 0
    {
        uint4 p0 = make_uint4(fp2bf2(aR[0].x, aR[0].y), fp2bf2(aR[0].z, aR[0].w),
                              fp2bf2(aR[1].x, aR[1].y), fp2bf2(aR[1].z, aR[1].w));
        uint4 p1 = make_uint4(fp2bf2(aR[2].x, aR[2].y), fp2bf2(aR[2].z, aR[2].w),
                              fp2bf2(aR[3].x, aR[3].y), fp2bf2(aR[3].z, aR[3].w));
        *(uint4*)(&As[0][arow][acol]) = p0;
        *(uint4*)(&As[0][arow][acol + 8]) = p1;
#pragma unroll
        for (int j = 0; j < 4; j++)
            *(uint32_t*)(&Ws[0][wnc][wk + 2 * j]) = fp2bf2(wF[2 * j], wF[2 * j + 1]);
    }
    __syncthreads();

    int nIter = K >> 5;
    for (int it = 0; it < nIter; it++) {
        int buf = it & 1;
        // issue LDG for next tile (hidden behind compute)
        if (it + 1 < nIter) {
            int k0 = (it + 1) << 5;
#pragma unroll
            for (int j = 0; j < 4; j++)
                aR[j] = *(const float4*)(apg + k0 + j * 4);
#pragma unroll
            for (int j = 0; j < 8; j++)
                wF[j] = wpg[(size_t)(k0 + j) * Nc];
        }
        // compute from buf: 2 k-chunks of 16
#pragma unroll
        for (int kc = 0; kc < 32; kc += 16) {
            uint32_t a[2][4], b[4][2];
#pragma unroll
            for (int i = 0; i < 2; i++) {
                const __nv_bfloat16* ar0 = &As[buf][wm + i * 16 + g][kc];
                const __nv_bfloat16* ar8 = &As[buf][wm + i * 16 + g + 8][kc];
                a[i][0] = *(const uint32_t*)(ar0 + 2 * t);
                a[i][1] = *(const uint32_t*)(ar8 + 2 * t);
                a[i][2] = *(const uint32_t*)(ar0 + 2 * t + 8);
                a[i][3] = *(const uint32_t*)(ar8 + 2 * t + 8);
            }
#pragma unroll
            for (int j = 0; j < 4; j++) {
                const __nv_bfloat16* wr = &Ws[buf][wn + j * 8 + g][kc];
                b[j][0] = *(const uint32_t*)(wr + 2 * t);
                b[j][1] = *(const uint32_t*)(wr + 2 * t + 8);
            }
#pragma unroll
            for (int i = 0; i < 2; i++)
#pragma unroll
                for (int j = 0; j < 4; j++) mma16816(c[i][j], a[i], b[j]);
        }
        // stage next tile into other buffer (overlaps other warps' MMA)
        if (it + 1 < nIter) {
            int nb = buf ^ 1;
            uint4 p0 = make_uint4(fp2bf2(aR[0].x, aR[0].y), fp2bf2(aR[0].z, aR[0].w),
                                  fp2bf2(aR[1].x, aR[1].y), fp2bf2(aR[1].z, aR[1].w));
            uint4 p1 = make_uint4(fp2bf2(aR[2].x, aR[2].y), fp2bf2(aR[2].z, aR[2].w),
                                  fp2bf2(aR[3].x, aR[3].y), fp2bf2(aR[3].z, aR[3].w));
            *(uint4*)(&As[nb][arow][acol]) = p0;
            *(uint4*)(&As[nb][arow][acol + 8]) = p1;
#pragma unroll
            for (int j = 0; j < 4; j++)
                *(uint32_t*)(&Ws[nb][wnc][wk + 2 * j]) =
                    fp2bf2(wF[2 * j], wF[2 * j + 1]);
        }
        __syncthreads();
    }

    // epilogue: bias (+relu) (+residual), fp32 out
#pragma unroll
    for (int i = 0; i < 2; i++) {
        int r = row0 + wm + i * 16 + g;
#pragma unroll
        for (int j = 0; j < 4; j++) {
            int cc = col0 + wn + j * 8 + 2 * t;
            float2 bv = *(const float2*)(bias + cc);
            float v0 = c[i][j][0] + bv.x, v1 = c[i][j][1] + bv.y;
            float v2 = c[i][j][2] + bv.x, v3 = c[i][j][3] + bv.y;
            if (RELU) {
                v0 = fmaxf(v0, 0.f); v1 = fmaxf(v1, 0.f);
                v2 = fmaxf(v2, 0.f); v3 = fmaxf(v3, 0.f);
            }
            if (RES) {
                float2 r0 = *(const float2*)(res + (size_t)r * Nc + cc);
                float2 r1 = *(const float2*)(res + (size_t)(r + 8) * Nc + cc);
                v0 += r0.x; v1 += r0.y; v2 += r1.x; v3 += r1.y;
            }
            *(float2*)(C + (size_t)r * Nc + cc) = make_float2(v0, v1);
            *(float2*)(C + (size_t)(r + 8) * Nc + cc) = make_float2(v2, v3);
        }
    }
}

// ---------------- RoPE + transpose: q*SC2 bf16, k bf16, v f16 ---------------
__global__ void __launch_bounds__(256) rope_kernel(const float* __restrict__ qkv,
                                                   const float* __restrict__ fc,
                                                   const float* __restrict__ fs,
                                                   __nv_bfloat16* __restrict__ q,
                                                   __nv_bfloat16* __restrict__ k,
                                                   __half* __restrict__ v) {
    int row = blockIdx.x * 8 + (threadIdx.x >> 5);  // (b*H + h)*N + n
    int lane = threadIdx.x & 31;
    int n = row & (Nn - 1);
    int h = (row >> 11) & (Hh - 1);
    int b = row >> 14;
    const float* src = qkv + ((size_t)(b * Nn + n)) * (3 * Dd) + h * dhd;
    size_t obase = (size_t)row * dhd;
    if (lane < 16) {
        float c = fc[n * 16 + lane];
        float sn = fs[n * 16 + lane];
        float qe = src[2 * lane], qo = src[2 * lane + 1];
        q[obase + 2 * lane] = __float2bfloat16((qe * c - qo * sn) * SC2);
        q[obase + 2 * lane + 1] = __float2bfloat16((qe * sn + qo * c) * SC2);
        float ke = src[256 + 2 * lane], ko = src[256 + 2 * lane + 1];
        k[obase + 2 * lane] = __float2bfloat16(ke * c - ko * sn);
        k[obase + 2 * lane + 1] = __float2bfloat16(ke * sn + ko * c);
    }
    v[obase + lane] = __float2half(src[512 + lane]);
}

// ---------------- FA2 flash attention: 256 thr, 128 q-rows ------------------
// bf16 QK MMA, f16 exp2 + f16 PV, row-sum via ones-column MMA.
// K/V tiles register-prefetched.
__global__ void __launch_bounds__(256) attn_mma_kernel(
    const __nv_bfloat16* __restrict__ Q,
    const __nv_bfloat16* __restrict__ K,
    const __half* __restrict__ V,
    float* __restrict__ Out) {
    __shared__ __nv_bfloat16 Ks[64][40];
    __shared__ __half Vt[32][72];

    int tid = threadIdx.x;
    int w = tid >> 5;
    int lane = tid & 31;
    int g = lane >> 2;
    int t = lane & 3;
    int bh = blockIdx.y;
    int q0 = blockIdx.x * 128;

    const __nv_bfloat16* Kb = K + (size_t)bh * Nn * dhd;
    const __half* Vb = V + (size_t)bh * Nn * dhd;

    int qrow = q0 + w * 16 + g;
    const __nv_bfloat16* Qr0 = Q + ((size_t)bh * Nn + qrow) * dhd;
    const __nv_bfloat16* Qr8 = Qr0 + 8 * dhd;
    uint32_t aQ[8];
#pragma unroll
    for (int ks = 0; ks < 2; ks++) {
        aQ[ks * 4 + 0] = *(const uint32_t*)(Qr0 + ks * 16 + 2 * t);
        aQ[ks * 4 + 1] = *(const uint32_t*)(Qr8 + ks * 16 + 2 * t);
        aQ[ks * 4 + 2] = *(const uint32_t*)(Qr0 + ks * 16 + 2 * t + 8);
        aQ[ks * 4 + 3] = *(const uint32_t*)(Qr8 + ks * 16 + 2 * t + 8);
    }

    float oacc[4][4] = {};
    float oL[4] = {};  // ones-column accumulator: row sums at t==0
    const uint32_t bONE = (g == 0) ? 0x3C003C00u : 0u;  // f16 ones col (n==0)
    uint32_t bL[2] = {bONE, bONE};

    // per-thread staging coords
    int krow = tid >> 2, kc = tid & 3;       // K: row, 16B chunk
    int vrow = tid >> 2, vq = tid & 3;       // V: row, 8-half chunk

    // prefetch first tile into registers
    uint4 kreg = *(const uint4*)(Kb + (size_t)krow * dhd + kc * 8);
    uint4 vreg = *(const uint4*)(Vb + (size_t)vrow * dhd + vq * 8);

    for (int t0 = 0; t0 < Nn; t0 += 64) {
        // stage K tile
        *(uint4*)(&Ks[krow][kc * 8]) = kreg;
        // stage V tile transposed
        {
            const __half* vh = (const __half*)&vreg;
#pragma unroll
            for (int j = 0; j < 8; j++) Vt[vq * 8 + j][vrow] = vh[j];
        }
        __syncthreads();
        // prefetch next tile (hidden behind compute)
        if (t0 + 64 < Nn) {
            kreg = *(const uint4*)(Kb + (size_t)(t0 + 64 + krow) * dhd + kc * 8);
            vreg = *(const uint4*)(Vb + (size_t)(t0 + 64 + vrow) * dhd + vq * 8);
        }

        // S = Qsc K^T (bf16)
        float cS[8][4];
#pragma unroll
        for (int n = 0; n < 8; n++) {
            cS[n][0] = cS[n][1] = cS[n][2] = cS[n][3] = 0.f;
            const __nv_bfloat16* kr = &Ks[n * 8 + g][0];
#pragma unroll
            for (int ks = 0; ks < 2; ks++) {
                uint32_t b[2];
                b[0] = *(const uint32_t*)(kr + ks * 16 + 2 * t);
                b[1] = *(const uint32_t*)(kr + ks * 16 + 2 * t + 8);
                mma16816(cS[n], &aQ[ks * 4], b);
            }
        }

        // p = exp2(S) in f16x2 (S pre-scaled by SC2 via Q)
        uint32_t pf[8][2];
#pragma unroll
        for (int n = 0; n < 8; n++) {
            __half2 lo = h2exp2(__floats2half2_rn(cS[n][0], cS[n][1]));
            __half2 hi = h2exp2(__floats2half2_rn(cS[n][2], cS[n][3]));
            pf[n][0] = *(uint32_t*)&lo;
            pf[n][1] = *(uint32_t*)&hi;
        }

        // O += P V (f16), plus ones-column for row sums
#pragma unroll
        for (int kk = 0; kk < 4; kk++) {
            uint32_t aP[4] = {pf[2 * kk][0], pf[2 * kk][1],
                              pf[2 * kk + 1][0], pf[2 * kk + 1][1]};
#pragma unroll
            for (int nd = 0; nd < 4; nd++) {
                const __half* vr = &Vt[nd * 8 + g][0];
                uint32_t b[2];
                b[0] = *(const uint32_t*)(vr + kk * 16 + 2 * t);
                b[1] = *(const uint32_t*)(vr + kk * 16 + 2 * t + 8);
                mma16816h(oacc[nd], aP, b);
            }
            mma16816h(oL, aP, bL);
        }
        __syncthreads();
    }

    // broadcast row sums from t==0 lane of each group
    float l0 = __shfl_sync(0xffffffffu, oL[0], lane & 28);
    float l1 = __shfl_sync(0xffffffffu, oL[2], lane & 28);
    float inv0 = 1.0f / l0;
    float inv1 = 1.0f / l1;

    int b = bh >> 3, h = bh & 7;
    size_t base0 = ((size_t)(b * Nn + qrow)) * Dd + h * dhd;
    size_t base1 = base0 + 8 * Dd;
#pragma unroll
    for (int nd = 0; nd < 4; nd++) {
        int col = nd * 8 + 2 * t;
        *(float2*)(Out + base0 + col) =
            make_float2(oacc[nd][0] * inv0, oacc[nd][1] * inv0);
        *(float2*)(Out + base1 + col) =
            make_float2(oacc[nd][2] * inv1, oacc[nd][3] * inv1);
    }
}

// ---------------- launch ---------------------------------------------------
extern "C" void kernel_launch(void* const* d_in, const int* in_sizes, int n_in,
                              void* d_out, int out_size) {
    const float* x      = (const float*)d_in[0];
    const float* fc     = (const float*)d_in[1];
    const float* fs     = (const float*)d_in[2];
    const float* w_qkv  = (const float*)d_in[3];
    const float* b_qkv  = (const float*)d_in[4];
    const float* w_proj = (const float*)d_in[5];
    const float* b_proj = (const float*)d_in[6];
    const float* ln1g   = (const float*)d_in[7];
    const float* ln1b   = (const float*)d_in[8];
    const float* ln2g   = (const float*)d_in[9];
    const float* ln2b   = (const float*)d_in[10];
    const float* w1     = (const float*)d_in[11];
    const float* b1     = (const float*)d_in[12];
    const float* w2     = (const float*)d_in[13];
    const float* b2     = (const float*)d_in[14];
    float* out = (float*)d_out;

    float *h, *qkv, *attn, *x2, *t;
    __nv_bfloat16 *qb, *kb;
    __half *vh;
    cudaGetSymbolAddress((void**)&h, g_h);
    cudaGetSymbolAddress((void**)&qkv, g_qkv);
    cudaGetSymbolAddress((void**)&qb, g_qb);
    cudaGetSymbolAddress((void**)&kb, g_kb);
    cudaGetSymbolAddress((void**)&vh, g_vh);
    cudaGetSymbolAddress((void**)&attn, g_attn);
    cudaGetSymbolAddress((void**)&x2, g_x2);
    cudaGetSymbolAddress((void**)&t, g_t);

    // 1) LN1
    ln_kernel<<<M_ROWS / 8, 256>>>(x, ln1g, ln1b, h);
    // 2) QKV gemm (bf16 TC)
    gemm_tc<false, false><<<dim3(768 / 64, M_ROWS / 128), 256>>>(
        h, w_qkv, b_qkv, nullptr, qkv, M_ROWS, 256, 768);
    // 3) RoPE + transpose
    rope_kernel<<<(Bb * Hh * Nn) / 8, 256>>>(qkv, fc, fs, qb, kb, vh);
    // 4) attention (128-row q-tiles, 8 warps)
    attn_mma_kernel<<<dim3(Nn / 128, Bb * Hh), 256>>>(qb, kb, vh, attn);
    // 5) proj + residual
    gemm_tc<false, true><<<dim3(256 / 64, M_ROWS / 128), 256>>>(
        attn, w_proj, b_proj, x, x2, M_ROWS, 256, 256);
    // 6) LN2
    ln_kernel<<<M_ROWS / 8, 256>>>(x2, ln2g, ln2b, h);
    // 7) FFN1 + relu
    gemm_tc<true, false><<<dim3(512 / 64, M_ROWS / 128), 256>>>(
        h, w1, b1, nullptr, t, M_ROWS, 256, 512);
    // 8) FFN2 + residual
    gemm_tc<false, true><<<dim3(256 / 64, M_ROWS / 128), 256>>>(
        t, w2, b2, x2, out, M_ROWS, 512, 256);
}

// round 16
// speedup vs baseline: 1.5250x; 1.1525x over previous
#include <cuda_runtime.h>
#include <cuda_bf16.h>
#include <cuda_fp16.h>
#include <math.h>
#include <stddef.h>
#include <stdint.h>

// Problem constants
#define Bb 4
#define Nn 2048
#define Dd 256
#define Hh 8
#define dhd 32
#define M_ROWS (Bb * Nn)            // 8192
#define EPSc 1e-5f
#define SC2 (0.17677669529663687f * 1.4426950408889634f) // scale * log2(e)

// ---------------- scratch (device globals; no allocation allowed) ----------
__device__ __nv_bfloat16 g_hb[M_ROWS * Dd];         // LN out, bf16
__device__ float g_qkv[M_ROWS * 3 * Dd];            // QKV out, f32 (rope reads)
__device__ __nv_bfloat16 g_qb[Bb * Hh * Nn * dhd];  // q * SC2, bf16
__device__ __nv_bfloat16 g_kb[Bb * Hh * Nn * dhd];
__device__ __half g_vh[Bb * Hh * Nn * dhd];         // v, f16
__device__ __nv_bfloat16 g_attnb[M_ROWS * Dd];      // attention out, bf16
__device__ float g_x2[M_ROWS * Dd];
__device__ __nv_bfloat16 g_tb[M_ROWS * 2 * Dd];     // ffn mid, bf16
// pre-converted transposed weights (bf16, [n][k])
__device__ __nv_bfloat16 g_wqkvT[3 * Dd * Dd];      // [768][256]
__device__ __nv_bfloat16 g_wprojT[Dd * Dd];         // [256][256]
__device__ __nv_bfloat16 g_w1T[2 * Dd * Dd];        // [512][256]
__device__ __nv_bfloat16 g_w2T[Dd * 2 * Dd];        // [256][512]

// ---------------- mma helpers ----------------------------------------------
__device__ __forceinline__ void mma16816(float* c, const uint32_t* a,
                                         const uint32_t* b) {
    asm volatile(
        "mma.sync.aligned.m16n8k16.row.col.f32.bf16.bf16.f32 "
        "{%0,%1,%2,%3}, {%4,%5,%6,%7}, {%8,%9}, {%0,%1,%2,%3};"
        : "+f"(c[0]), "+f"(c[1]), "+f"(c[2]), "+f"(c[3])
        : "r"(a[0]), "r"(a[1]), "r"(a[2]), "r"(a[3]), "r"(b[0]), "r"(b[1]));
}
__device__ __forceinline__ void mma16816h(float* c, const uint32_t* a,
                                          const uint32_t* b) {
    asm volatile(
        "mma.sync.aligned.m16n8k16.row.col.f32.f16.f16.f32 "
        "{%0,%1,%2,%3}, {%4,%5,%6,%7}, {%8,%9}, {%0,%1,%2,%3};"
        : "+f"(c[0]), "+f"(c[1]), "+f"(c[2]), "+f"(c[3])
        : "r"(a[0]), "r"(a[1]), "r"(a[2]), "r"(a[3]), "r"(b[0]), "r"(b[1]));
}
__device__ __forceinline__ uint32_t fp2bf2(float lo, float hi) {
    __nv_bfloat162 h = __floats2bfloat162_rn(lo, hi);
    return *(uint32_t*)&h;
}

// ---------------- weight convert + transpose: f32 [K][Nc] -> bf16 [Nc][K] ---
__global__ void __launch_bounds__(256) wcvt_kernel(const float* __restrict__ W,
                                                   __nv_bfloat16* __restrict__ WT,
                                                   int K, int Nc) {
    __shared__ float tile[32][33];
    int tx = threadIdx.x & 31, ty = threadIdx.x >> 5;  // 32 x 8
    int n0 = blockIdx.x * 32, k0 = blockIdx.y * 32;
#pragma unroll
    for (int j = 0; j < 4; j++)
        tile[ty + 8 * j][tx] = W[(size_t)(k0 + ty + 8 * j) * Nc + n0 + tx];
    __syncthreads();
#pragma unroll
    for (int j = 0; j < 4; j++)
        WT[(size_t)(n0 + ty + 8 * j) * K + k0 + tx] =
            __float2bfloat16(tile[tx][ty + 8 * j]);
}

// ---------------- LayerNorm (bf16 output) -----------------------------------
__global__ void __launch_bounds__(256) ln_kernel(const float* __restrict__ x,
                                                 const float* __restrict__ g,
                                                 const float* __restrict__ b,
                                                 __nv_bfloat16* __restrict__ out) {
    int row = blockIdx.x * 8 + (threadIdx.x >> 5);
    int lane = threadIdx.x & 31;
    const float4* xr = (const float4*)(x + (size_t)row * Dd);
    float4 v0 = xr[lane];
    float4 v1 = xr[lane + 32];
    float s = v0.x + v0.y + v0.z + v0.w + v1.x + v1.y + v1.z + v1.w;
#pragma unroll
    for (int o = 16; o; o >>= 1) s += __shfl_xor_sync(0xffffffffu, s, o);
    float mu = s * (1.0f / Dd);
    float a0 = v0.x - mu, a1 = v0.y - mu, a2 = v0.z - mu, a3 = v0.w - mu;
    float a4 = v1.x - mu, a5 = v1.y - mu, a6 = v1.z - mu, a7 = v1.w - mu;
    float ss = a0 * a0 + a1 * a1 + a2 * a2 + a3 * a3 + a4 * a4 + a5 * a5 +
               a6 * a6 + a7 * a7;
#pragma unroll
    for (int o = 16; o; o >>= 1) ss += __shfl_xor_sync(0xffffffffu, ss, o);
    float inv = rsqrtf(ss * (1.0f / Dd) + EPSc);
    const float4* g4 = (const float4*)g;
    const float4* b4 = (const float4*)b;
    float4 g0 = g4[lane], g1 = g4[lane + 32];
    float4 bb0 = b4[lane], bb1 = b4[lane + 32];
    __nv_bfloat16* orow = out + (size_t)row * Dd;
    *(uint2*)(orow + lane * 4) = make_uint2(
        fp2bf2(a0 * inv * g0.x + bb0.x, a1 * inv * g0.y + bb0.y),
        fp2bf2(a2 * inv * g0.z + bb0.z, a3 * inv * g0.w + bb0.w));
    *(uint2*)(orow + 128 + lane * 4) = make_uint2(
        fp2bf2(a4 * inv * g1.x + bb1.x, a5 * inv * g1.y + bb1.y),
        fp2bf2(a6 * inv * g1.z + bb1.z, a7 * inv * g1.w + bb1.w));
}

// ---------------- bf16-native GEMM: A[M,K]bf16 @ WT[Nc,K]bf16 ---------------
// Block tile 128Mx64N, BK=32, 256 thr (8 warps 4x2), warp tile 32x32.
// Double-buffered smem + register prefetch; zero cvt in the mainloop.
template <bool RELU, bool RES, bool OUTBF>
__global__ void __launch_bounds__(256) gemm_bf(const __nv_bfloat16* __restrict__ A,
                                               const __nv_bfloat16* __restrict__ WT,
                                               const float* __restrict__ bias,
                                               const float* __restrict__ res,
                                               void* __restrict__ Cv,
                                               int M, int K, int Nc) {
    __shared__ __nv_bfloat16 As[2][128][40];
    __shared__ __nv_bfloat16 Ws[2][64][40];

    int tid = threadIdx.x;
    int w = tid >> 5, lane = tid & 31;
    int g = lane >> 2, t = lane & 3;
    int wm = (w & 3) * 32, wn = (w >> 2) * 32;
    int row0 = blockIdx.y * 128, col0 = blockIdx.x * 64;

    float c[2][4][4] = {};

    // A staging: thread owns chunks tid and tid+256 (row, 16B seg)
    int ar = tid >> 2, as = tid & 3;
    const __nv_bfloat16* apg = A + (size_t)row0 * K + as * 8;
    // W staging: thread owns one uint4 of WT
    int wr = tid >> 2, ws = tid & 3;
    const __nv_bfloat16* wpg = WT + (size_t)(col0 + wr) * K + ws * 8;

    uint4 aRg0 = *(const uint4*)(apg + (size_t)ar * K);
    uint4 aRg1 = *(const uint4*)(apg + (size_t)(ar + 64) * K);
    uint4 wRg = *(const uint4*)(wpg);
    *(uint4*)(&As[0][ar][as * 8]) = aRg0;
    *(uint4*)(&As[0][ar + 64][as * 8]) = aRg1;
    *(uint4*)(&Ws[0][wr][ws * 8]) = wRg;
    __syncthreads();

    int nIter = K >> 5;
    for (int it = 0; it < nIter; it++) {
        int buf = it & 1;
        if (it + 1 < nIter) {
            int k0 = (it + 1) << 5;
            aRg0 = *(const uint4*)(apg + (size_t)ar * K + k0);
            aRg1 = *(const uint4*)(apg + (size_t)(ar + 64) * K + k0);
            wRg = *(const uint4*)(wpg + k0);
        }
#pragma unroll
        for (int kc = 0; kc < 32; kc += 16) {
            uint32_t a[2][4], b[4][2];
#pragma unroll
            for (int i = 0; i < 2; i++) {
                const __nv_bfloat16* ar0 = &As[buf][wm + i * 16 + g][kc];
                const __nv_bfloat16* ar8 = &As[buf][wm + i * 16 + g + 8][kc];
                a[i][0] = *(const uint32_t*)(ar0 + 2 * t);
                a[i][1] = *(const uint32_t*)(ar8 + 2 * t);
                a[i][2] = *(const uint32_t*)(ar0 + 2 * t + 8);
                a[i][3] = *(const uint32_t*)(ar8 + 2 * t + 8);
            }
#pragma unroll
            for (int j = 0; j < 4; j++) {
                const __nv_bfloat16* wrp = &Ws[buf][wn + j * 8 + g][kc];
                b[j][0] = *(const uint32_t*)(wrp + 2 * t);
                b[j][1] = *(const uint32_t*)(wrp + 2 * t + 8);
            }
#pragma unroll
            for (int i = 0; i < 2; i++)
#pragma unroll
                for (int j = 0; j < 4; j++) mma16816(c[i][j], a[i], b[j]);
        }
        if (it + 1 < nIter) {
            int nb = buf ^ 1;
            *(uint4*)(&As[nb][ar][as * 8]) = aRg0;
            *(uint4*)(&As[nb][ar + 64][as * 8]) = aRg1;
            *(uint4*)(&Ws[nb][wr][ws * 8]) = wRg;
        }
        __syncthreads();
    }

    // epilogue
#pragma unroll
    for (int i = 0; i < 2; i++) {
        int r = row0 + wm + i * 16 + g;
#pragma unroll
        for (int j = 0; j < 4; j++) {
            int cc = col0 + wn + j * 8 + 2 * t;
            float2 bv = *(const float2*)(bias + cc);
            float v0 = c[i][j][0] + bv.x, v1 = c[i][j][1] + bv.y;
            float v2 = c[i][j][2] + bv.x, v3 = c[i][j][3] + bv.y;
            if (RELU) {
                v0 = fmaxf(v0, 0.f); v1 = fmaxf(v1, 0.f);
                v2 = fmaxf(v2, 0.f); v3 = fmaxf(v3, 0.f);
            }
            if (RES) {
                float2 r0 = *(const float2*)(res + (size_t)r * Nc + cc);
                float2 r1 = *(const float2*)(res + (size_t)(r + 8) * Nc + cc);
                v0 += r0.x; v1 += r0.y; v2 += r1.x; v3 += r1.y;
            }
            if (OUTBF) {
                __nv_bfloat16* C = (__nv_bfloat16*)Cv;
                *(uint32_t*)(C + (size_t)r * Nc + cc) = fp2bf2(v0, v1);
                *(uint32_t*)(C + (size_t)(r + 8) * Nc + cc) = fp2bf2(v2, v3);
            } else {
                float* C = (float*)Cv;
                *(float2*)(C + (size_t)r * Nc + cc) = make_float2(v0, v1);
                *(float2*)(C + (size_t)(r + 8) * Nc + cc) = make_float2(v2, v3);
            }
        }
    }
}

// ---------------- RoPE + transpose: q*SC2 bf16, k bf16, v f16 ---------------
__global__ void __launch_bounds__(256) rope_kernel(const float* __restrict__ qkv,
                                                   const float* __restrict__ fc,
                                                   const float* __restrict__ fs,
                                                   __nv_bfloat16* __restrict__ q,
                                                   __nv_bfloat16* __restrict__ k,
                                                   __half* __restrict__ v) {
    int row = blockIdx.x * 8 + (threadIdx.x >> 5);  // (b*H + h)*N + n
    int lane = threadIdx.x & 31;
    int n = row & (Nn - 1);
    int h = (row >> 11) & (Hh - 1);
    int b = row >> 14;
    const float* src = qkv + ((size_t)(b * Nn + n)) * (3 * Dd) + h * dhd;
    size_t obase = (size_t)row * dhd;
    if (lane < 16) {
        float c = fc[n * 16 + lane];
        float sn = fs[n * 16 + lane];
        float qe = src[2 * lane], qo = src[2 * lane + 1];
        q[obase + 2 * lane] = __float2bfloat16((qe * c - qo * sn) * SC2);
        q[obase + 2 * lane + 1] = __float2bfloat16((qe * sn + qo * c) * SC2);
        float ke = src[256 + 2 * lane], ko = src[256 + 2 * lane + 1];
        k[obase + 2 * lane] = __float2bfloat16(ke * c - ko * sn);
        k[obase + 2 * lane + 1] = __float2bfloat16(ke * sn + ko * c);
    }
    v[obase + lane] = __float2half(src[512 + lane]);
}

// ---------------- FA2 flash attention: 256 thr, 128 q-rows (bf16 out) -------
__global__ void __launch_bounds__(256) attn_mma_kernel(
    const __nv_bfloat16* __restrict__ Q,
    const __nv_bfloat16* __restrict__ K,
    const __half* __restrict__ V,
    __nv_bfloat16* __restrict__ Out) {
    __shared__ __nv_bfloat16 Ks[64][40];
    __shared__ __half Vt[32][72];

    int tid = threadIdx.x;
    int w = tid >> 5;
    int lane = tid & 31;
    int g = lane >> 2;
    int t = lane & 3;
    int bh = blockIdx.y;
    int q0 = blockIdx.x * 128;

    const __nv_bfloat16* Kb = K + (size_t)bh * Nn * dhd;
    const __half* Vb = V + (size_t)bh * Nn * dhd;

    int qrow = q0 + w * 16 + g;
    const __nv_bfloat16* Qr0 = Q + ((size_t)bh * Nn + qrow) * dhd;
    const __nv_bfloat16* Qr8 = Qr0 + 8 * dhd;
    uint32_t aQ[8];
#pragma unroll
    for (int ks = 0; ks < 2; ks++) {
        aQ[ks * 4 + 0] = *(const uint32_t*)(Qr0 + ks * 16 + 2 * t);
        aQ[ks * 4 + 1] = *(const uint32_t*)(Qr8 + ks * 16 + 2 * t);
        aQ[ks * 4 + 2] = *(const uint32_t*)(Qr0 + ks * 16 + 2 * t + 8);
        aQ[ks * 4 + 3] = *(const uint32_t*)(Qr8 + ks * 16 + 2 * t + 8);
    }

    float oacc[4][4] = {};
    float oL[4] = {};
    const uint32_t bONE = (g == 0) ? 0x3C003C00u : 0u;
    uint32_t bL[2] = {bONE, bONE};

    int krow = tid >> 2, kc = tid & 3;
    int vrow = tid >> 2, vq = tid & 3;

    uint4 kreg = *(const uint4*)(Kb + (size_t)krow * dhd + kc * 8);
    uint4 vreg = *(const uint4*)(Vb + (size_t)vrow * dhd + vq * 8);

    for (int t0 = 0; t0 < Nn; t0 += 64) {
        *(uint4*)(&Ks[krow][kc * 8]) = kreg;
        {
            const __half* vh = (const __half*)&vreg;
#pragma unroll
            for (int j = 0; j < 8; j++) Vt[vq * 8 + j][vrow] = vh[j];
        }
        __syncthreads();
        if (t0 + 64 < Nn) {
            kreg = *(const uint4*)(Kb + (size_t)(t0 + 64 + krow) * dhd + kc * 8);
            vreg = *(const uint4*)(Vb + (size_t)(t0 + 64 + vrow) * dhd + vq * 8);
        }

        float cS[8][4];
#pragma unroll
        for (int n = 0; n < 8; n++) {
            cS[n][0] = cS[n][1] = cS[n][2] = cS[n][3] = 0.f;
            const __nv_bfloat16* kr = &Ks[n * 8 + g][0];
#pragma unroll
            for (int ks = 0; ks < 2; ks++) {
                uint32_t b[2];
                b[0] = *(const uint32_t*)(kr + ks * 16 + 2 * t);
                b[1] = *(const uint32_t*)(kr + ks * 16 + 2 * t + 8);
                mma16816(cS[n], &aQ[ks * 4], b);
            }
        }

        uint32_t pf[8][2];
#pragma unroll
        for (int n = 0; n < 8; n++) {
            __half2 lo = h2exp2(__floats2half2_rn(cS[n][0], cS[n][1]));
            __half2 hi = h2exp2(__floats2half2_rn(cS[n][2], cS[n][3]));
            pf[n][0] = *(uint32_t*)&lo;
            pf[n][1] = *(uint32_t*)&hi;
        }

#pragma unroll
        for (int kk = 0; kk < 4; kk++) {
            uint32_t aP[4] = {pf[2 * kk][0], pf[2 * kk][1],
                              pf[2 * kk + 1][0], pf[2 * kk + 1][1]};
#pragma unroll
            for (int nd = 0; nd < 4; nd++) {
                const __half* vr = &Vt[nd * 8 + g][0];
                uint32_t b[2];
                b[0] = *(const uint32_t*)(vr + kk * 16 + 2 * t);
                b[1] = *(const uint32_t*)(vr + kk * 16 + 2 * t + 8);
                mma16816h(oacc[nd], aP, b);
            }
            mma16816h(oL, aP, bL);
        }
        __syncthreads();
    }

    float l0 = __shfl_sync(0xffffffffu, oL[0], lane & 28);
    float l1 = __shfl_sync(0xffffffffu, oL[2], lane & 28);
    float inv0 = 1.0f / l0;
    float inv1 = 1.0f / l1;

    int b = bh >> 3, h = bh & 7;
    size_t base0 = ((size_t)(b * Nn + qrow)) * Dd + h * dhd;
    size_t base1 = base0 + 8 * Dd;
#pragma unroll
    for (int nd = 0; nd < 4; nd++) {
        int col = nd * 8 + 2 * t;
        *(uint32_t*)(Out + base0 + col) =
            fp2bf2(oacc[nd][0] * inv0, oacc[nd][1] * inv0);
        *(uint32_t*)(Out + base1 + col) =
            fp2bf2(oacc[nd][2] * inv1, oacc[nd][3] * inv1);
    }
}

// ---------------- launch ---------------------------------------------------
extern "C" void kernel_launch(void* const* d_in, const int* in_sizes, int n_in,
                              void* d_out, int out_size) {
    const float* x      = (const float*)d_in[0];
    const float* fc     = (const float*)d_in[1];
    const float* fs     = (const float*)d_in[2];
    const float* w_qkv  = (const float*)d_in[3];
    const float* b_qkv  = (const float*)d_in[4];
    const float* w_proj = (const float*)d_in[5];
    const float* b_proj = (const float*)d_in[6];
    const float* ln1g   = (const float*)d_in[7];
    const float* ln1b   = (const float*)d_in[8];
    const float* ln2g   = (const float*)d_in[9];
    const float* ln2b   = (const float*)d_in[10];
    const float* w1     = (const float*)d_in[11];
    const float* b1     = (const float*)d_in[12];
    const float* w2     = (const float*)d_in[13];
    const float* b2     = (const float*)d_in[14];
    float* out = (float*)d_out;

    float *qkv, *x2;
    __nv_bfloat16 *hb, *qb, *kb, *attnb, *tb;
    __nv_bfloat16 *wqkvT, *wprojT, *w1T, *w2T;
    __half *vh;
    cudaGetSymbolAddress((void**)&hb, g_hb);
    cudaGetSymbolAddress((void**)&qkv, g_qkv);
    cudaGetSymbolAddress((void**)&qb, g_qb);
    cudaGetSymbolAddress((void**)&kb, g_kb);
    cudaGetSymbolAddress((void**)&vh, g_vh);
    cudaGetSymbolAddress((void**)&attnb, g_attnb);
    cudaGetSymbolAddress((void**)&x2, g_x2);
    cudaGetSymbolAddress((void**)&tb, g_tb);
    cudaGetSymbolAddress((void**)&wqkvT, g_wqkvT);
    cudaGetSymbolAddress((void**)&wprojT, g_wprojT);
    cudaGetSymbolAddress((void**)&w1T, g_w1T);
    cudaGetSymbolAddress((void**)&w2T, g_w2T);

    // 0) pre-convert weights to bf16 [n][k]
    wcvt_kernel<<<dim3(768 / 32, 256 / 32), 256>>>(w_qkv, wqkvT, 256, 768);
    wcvt_kernel<<<dim3(256 / 32, 256 / 32), 256>>>(w_proj, wprojT, 256, 256);
    wcvt_kernel<<<dim3(512 / 32, 256 / 32), 256>>>(w1, w1T, 256, 512);
    wcvt_kernel<<<dim3(256 / 32, 512 / 32), 256>>>(w2, w2T, 512, 256);

    // 1) LN1 (bf16 out)
    ln_kernel<<<M_ROWS / 8, 256>>>(x, ln1g, ln1b, hb);
    // 2) QKV gemm (bf16-native, f32 out)
    gemm_bf<false, false, false><<<dim3(768 / 64, M_ROWS / 128), 256>>>(
        hb, wqkvT, b_qkv, nullptr, qkv, M_ROWS, 256, 768);
    // 3) RoPE + transpose
    rope_kernel<<<(Bb * Hh * Nn) / 8, 256>>>(qkv, fc, fs, qb, kb, vh);
    // 4) attention (bf16 out)
    attn_mma_kernel<<<dim3(Nn / 128, Bb * Hh), 256>>>(qb, kb, vh, attnb);
    // 5) proj + residual (f32 out)
    gemm_bf<false, true, false><<<dim3(256 / 64, M_ROWS / 128), 256>>>(
        attnb, wprojT, b_proj, x, x2, M_ROWS, 256, 256);
    // 6) LN2 (bf16 out)
    ln_kernel<<<M_ROWS / 8, 256>>>(x2, ln2g, ln2b, hb);
    // 7) FFN1 + relu (bf16 out)
    gemm_bf<true, false, true><<<dim3(512 / 64, M_ROWS / 128), 256>>>(
        hb, w1T, b1, nullptr, tb, M_ROWS, 256, 512);
    // 8) FFN2 + residual (f32 out)
    gemm_bf<false, true, false><<<dim3(256 / 64, M_ROWS / 128), 256>>>(
        tb, w2T, b2, x2, out, M_ROWS, 512, 256);
}